// round 2
// baseline (speedup 1.0000x reference)
#include <cuda_runtime.h>
#include <cuda_bf16.h>
#include <cstdint>
#include <cstddef>

// Problem constants
#define BATCH   4
#define SEQ     2048
#define DMODEL  512
#define NHEADS  8
#define HDIM    64
#define DFF     2048
#define NLAYERS 6
#define MROWS   (BATCH * SEQ)            // 8192

// -------- scratch (device globals; no allocation allowed) --------
__device__ float g_x   [MROWS * DMODEL];
__device__ float g_q   [MROWS * DMODEL];
__device__ float g_k   [MROWS * DMODEL];
__device__ float g_v   [MROWS * DMODEL];
__device__ float g_attn[MROWS * DMODEL];
__device__ float g_tmp [MROWS * DMODEL];
__device__ float g_ff  [MROWS * DFF];

// =====================================================================
// Embedding + positional encoding:  x[b,l,:] = embed[src[b,l],:] + pe[l,:]
// grid = 8192 blocks, 128 threads (float4 per thread)
// =====================================================================
__global__ void __launch_bounds__(128) embed_kernel(
    const int* __restrict__ src, const float* __restrict__ emb,
    const float* __restrict__ pe, float* __restrict__ x)
{
    int bl  = blockIdx.x;          // b*SEQ + l
    int l   = bl & (SEQ - 1);
    int tok = src[bl];
    int c   = threadIdx.x * 4;
    float4 e = *(const float4*)(emb + (size_t)tok * DMODEL + c);
    float4 p = *(const float4*)(pe  + (size_t)l   * DMODEL + c);
    float4 o; o.x = e.x + p.x; o.y = e.y + p.y; o.z = e.z + p.z; o.w = e.w + p.w;
    *(float4*)(x + (size_t)bl * DMODEL + c) = o;
}

// =====================================================================
// GEMM: C[M,N] = A[M,K] @ W[K,N] + bias (+ residual) (+relu)
// 128x128 block tile, 8 k-slice, 256 threads, 8x8 per thread,
// smem double buffered with register staging.
// Requires: M%128==0, N%128==0, K%8==0.
// =====================================================================
__global__ void __launch_bounds__(256) gemm_kernel(
    const float* __restrict__ A, const float* __restrict__ W,
    const float* __restrict__ bias, const float* __restrict__ res,
    float* __restrict__ C, int M, int N, int K, int relu)
{
    __shared__ __align__(16) float As[2][8][128];
    __shared__ __align__(16) float Bs[2][8][128];

    int tid = threadIdx.x;
    int tx  = tid & 15;
    int ty  = tid >> 4;
    int bm  = blockIdx.y << 7;
    int bn  = blockIdx.x << 7;

    const float* Ag = A + (size_t)(bm + (tid >> 1)) * K + (tid & 1) * 4;
    const float* Bg = W + (size_t)(tid >> 5) * N + bn + (tid & 31) * 4;

    float acc[8][8];
#pragma unroll
    for (int i = 0; i < 8; i++)
#pragma unroll
        for (int j = 0; j < 8; j++) acc[i][j] = 0.f;

    int nt = K >> 3;
    float4 af = *(const float4*)Ag;
    float4 bf = *(const float4*)Bg;
    {
        int kc = (tid & 1) * 4, mr = tid >> 1;
        As[0][kc + 0][mr] = af.x; As[0][kc + 1][mr] = af.y;
        As[0][kc + 2][mr] = af.z; As[0][kc + 3][mr] = af.w;
        *(float4*)&Bs[0][tid >> 5][(tid & 31) * 4] = bf;
    }
    __syncthreads();

    for (int kt = 0; kt < nt; kt++) {
        int cur = kt & 1;
        if (kt + 1 < nt) {
            af = *(const float4*)(Ag + (size_t)(kt + 1) * 8);
            bf = *(const float4*)(Bg + (size_t)(kt + 1) * 8 * N);
        }
#pragma unroll
        for (int kk = 0; kk < 8; kk++) {
            float4 a0 = *(const float4*)&As[cur][kk][ty * 4];
            float4 a1 = *(const float4*)&As[cur][kk][64 + ty * 4];
            float4 b0 = *(const float4*)&Bs[cur][kk][tx * 4];
            float4 b1 = *(const float4*)&Bs[cur][kk][64 + tx * 4];
            float av[8] = {a0.x, a0.y, a0.z, a0.w, a1.x, a1.y, a1.z, a1.w};
            float bv[8] = {b0.x, b0.y, b0.z, b0.w, b1.x, b1.y, b1.z, b1.w};
#pragma unroll
            for (int i = 0; i < 8; i++)
#pragma unroll
                for (int j = 0; j < 8; j++) acc[i][j] += av[i] * bv[j];
        }
        if (kt + 1 < nt) {
            int nb = cur ^ 1;
            int kc = (tid & 1) * 4, mr = tid >> 1;
            As[nb][kc + 0][mr] = af.x; As[nb][kc + 1][mr] = af.y;
            As[nb][kc + 2][mr] = af.z; As[nb][kc + 3][mr] = af.w;
            *(float4*)&Bs[nb][tid >> 5][(tid & 31) * 4] = bf;
        }
        __syncthreads();
    }

    // epilogue
    float4 bia[2];
    bia[0] = *(const float4*)(bias + bn + tx * 4);
    bia[1] = *(const float4*)(bias + bn + 64 + tx * 4);
#pragma unroll
    for (int rg = 0; rg < 2; rg++) {
#pragma unroll
        for (int i = 0; i < 4; i++) {
            int row = bm + rg * 64 + ty * 4 + i;
            float* crow = C + (size_t)row * N;
            const float* rrow = res ? (res + (size_t)row * N) : nullptr;
#pragma unroll
            for (int cg = 0; cg < 2; cg++) {
                int col = bn + cg * 64 + tx * 4;
                const float* ap = &acc[rg * 4 + i][cg * 4];
                float4 o;
                o.x = ap[0] + ((const float*)&bia[cg])[0];
                o.y = ap[1] + ((const float*)&bia[cg])[1];
                o.z = ap[2] + ((const float*)&bia[cg])[2];
                o.w = ap[3] + ((const float*)&bia[cg])[3];
                if (rrow) {
                    float4 r4 = *(const float4*)(rrow + col);
                    o.x += r4.x; o.y += r4.y; o.z += r4.z; o.w += r4.w;
                }
                if (relu) {
                    o.x = fmaxf(o.x, 0.f); o.y = fmaxf(o.y, 0.f);
                    o.z = fmaxf(o.z, 0.f); o.w = fmaxf(o.w, 0.f);
                }
                *(float4*)(crow + col) = o;
            }
        }
    }
}

// =====================================================================
// Flash attention. Heads are CONTIGUOUS [2048,64] slabs (reference
// reshapes with no transpose). grid = (32 qtiles, 32 b*h), 256 threads.
// Tile: 64 queries x 64 keys, hd = 64. Online softmax in registers via
// width-16 butterfly shuffles. Output scattered to [B, L, H*64] layout.
// =====================================================================
#define AST 68   // padded smem row stride (floats); 68*4 = 272 B (16B mult)
#define ATTN_SMEM (4 * 64 * AST * 4)

__global__ void __launch_bounds__(256) attn_kernel(
    const float* __restrict__ q, const float* __restrict__ k,
    const float* __restrict__ v, float* __restrict__ out)
{
    extern __shared__ float sm[];
    float* Qs = sm;
    float* Ks = Qs + 64 * AST;
    float* Vs = Ks + 64 * AST;
    float* Ss = Vs + 64 * AST;

    int tid = threadIdx.x;
    int tx  = tid & 15;
    int ty  = tid >> 4;
    int bh  = blockIdx.y;          // b*8 + h
    int qt  = blockIdx.x;
    int b   = bh >> 3, h = bh & 7;

    const float* Qg = q + ((size_t)bh * SEQ + qt * 64) * HDIM;
    const float* Kg = k + (size_t)bh * SEQ * HDIM;
    const float* Vg = v + (size_t)bh * SEQ * HDIM;
    float* Og = out + ((size_t)b * SEQ + qt * 64) * DMODEL + h * HDIM;

    // load Q tile (64x64) -> smem : each thread loads 4 rows (row, row+16, ...)
    {
        int c = (tid & 15) * 4;
#pragma unroll
        for (int r = 0; r < 4; r++) {
            int row = (tid >> 4) + r * 16;
            *(float4*)(Qs + row * AST + c) = *(const float4*)(Qg + row * 64 + c);
        }
    }

    float m_i[4], l_i[4], o_acc[4][4];
#pragma unroll
    for (int i = 0; i < 4; i++) {
        m_i[i] = -1e30f; l_i[i] = 0.f;
#pragma unroll
        for (int j = 0; j < 4; j++) o_acc[i][j] = 0.f;
    }

    for (int kt = 0; kt < SEQ / 64; kt++) {
        __syncthreads();   // prev iter done with Ks/Vs/Ss; Q load visible on kt=0
        {
            int c = (tid & 15) * 4;
#pragma unroll
            for (int r = 0; r < 4; r++) {
                int row = (tid >> 4) + r * 16;
                *(float4*)(Ks + row * AST + c) =
                    *(const float4*)(Kg + (size_t)(kt * 64 + row) * 64 + c);
                *(float4*)(Vs + row * AST + c) =
                    *(const float4*)(Vg + (size_t)(kt * 64 + row) * 64 + c);
            }
        }
        __syncthreads();

        // ---- S = (Q K^T) * 0.125 : rows ty*4+i, cols tx+16*j ----
        float s[4][4];
#pragma unroll
        for (int i = 0; i < 4; i++)
#pragma unroll
            for (int j = 0; j < 4; j++) s[i][j] = 0.f;

#pragma unroll
        for (int kc = 0; kc < 16; kc++) {
            float4 a[4], bb[4];
#pragma unroll
            for (int i = 0; i < 4; i++)
                a[i] = *(const float4*)(Qs + (ty * 4 + i) * AST + kc * 4);
#pragma unroll
            for (int j = 0; j < 4; j++)
                bb[j] = *(const float4*)(Ks + (tx + 16 * j) * AST + kc * 4);
#pragma unroll
            for (int i = 0; i < 4; i++)
#pragma unroll
                for (int j = 0; j < 4; j++)
                    s[i][j] += a[i].x * bb[j].x + a[i].y * bb[j].y +
                               a[i].z * bb[j].z + a[i].w * bb[j].w;
        }
#pragma unroll
        for (int i = 0; i < 4; i++)
#pragma unroll
            for (int j = 0; j < 4; j++) s[i][j] *= 0.125f;

        // ---- online softmax (row groups = 16-lane half warps) ----
        float corr[4];
#pragma unroll
        for (int i = 0; i < 4; i++) {
            float mt = fmaxf(fmaxf(s[i][0], s[i][1]), fmaxf(s[i][2], s[i][3]));
#pragma unroll
            for (int off = 1; off < 16; off <<= 1)
                mt = fmaxf(mt, __shfl_xor_sync(0xffffffffu, mt, off, 16));
            float m_new = fmaxf(m_i[i], mt);
            corr[i] = __expf(m_i[i] - m_new);
            float rs = 0.f;
#pragma unroll
            for (int j = 0; j < 4; j++) {
                float p = __expf(s[i][j] - m_new);
                s[i][j] = p;
                rs += p;
            }
#pragma unroll
            for (int off = 1; off < 16; off <<= 1)
                rs += __shfl_xor_sync(0xffffffffu, rs, off, 16);
            l_i[i] = l_i[i] * corr[i] + rs;
            m_i[i] = m_new;
#pragma unroll
            for (int j = 0; j < 4; j++) o_acc[i][j] *= corr[i];
        }

        // write P to smem
#pragma unroll
        for (int i = 0; i < 4; i++)
#pragma unroll
            for (int j = 0; j < 4; j++)
                Ss[(ty * 4 + i) * AST + tx + 16 * j] = s[i][j];
        __syncthreads();

        // ---- O += P @ V : rows ty*4+i, dims tx*4+j ----
#pragma unroll
        for (int kc = 0; kc < 16; kc++) {
            float4 a[4];
#pragma unroll
            for (int i = 0; i < 4; i++)
                a[i] = *(const float4*)(Ss + (ty * 4 + i) * AST + kc * 4);
#pragma unroll
            for (int t = 0; t < 4; t++) {
                float4 bv = *(const float4*)(Vs + (kc * 4 + t) * AST + tx * 4);
#pragma unroll
                for (int i = 0; i < 4; i++) {
                    float av = ((const float*)&a[i])[t];
                    o_acc[i][0] += av * bv.x;
                    o_acc[i][1] += av * bv.y;
                    o_acc[i][2] += av * bv.z;
                    o_acc[i][3] += av * bv.w;
                }
            }
        }
    }

    // epilogue: divide by l, scatter to [B, L, H*64 + d]
#pragma unroll
    for (int i = 0; i < 4; i++) {
        float inv = 1.0f / l_i[i];
        float4 o;
        o.x = o_acc[i][0] * inv; o.y = o_acc[i][1] * inv;
        o.z = o_acc[i][2] * inv; o.w = o_acc[i][3] * inv;
        *(float4*)(Og + (size_t)(ty * 4 + i) * DMODEL + tx * 4) = o;
    }
}

// =====================================================================
// LayerNorm over last dim (512). Block per row, 128 threads.
// =====================================================================
__global__ void __launch_bounds__(128) ln_kernel(
    const float* __restrict__ in, const float* __restrict__ g,
    const float* __restrict__ b, float* __restrict__ out)
{
    int row = blockIdx.x;
    int tid = threadIdx.x;
    float4 v4 = *(const float4*)(in + (size_t)row * DMODEL + tid * 4);
    float s  = v4.x + v4.y + v4.z + v4.w;
    float sq = v4.x * v4.x + v4.y * v4.y + v4.z * v4.z + v4.w * v4.w;
#pragma unroll
    for (int off = 16; off > 0; off >>= 1) {
        s  += __shfl_xor_sync(0xffffffffu, s, off);
        sq += __shfl_xor_sync(0xffffffffu, sq, off);
    }
    __shared__ float ss[4], sqs[4];
    int wid = tid >> 5;
    if ((tid & 31) == 0) { ss[wid] = s; sqs[wid] = sq; }
    __syncthreads();
    s  = ss[0] + ss[1] + ss[2] + ss[3];
    sq = sqs[0] + sqs[1] + sqs[2] + sqs[3];
    float mu  = s * (1.0f / DMODEL);
    float var = sq * (1.0f / DMODEL) - mu * mu;
    float inv = rsqrtf(var + 1e-5f);
    float4 gv = *(const float4*)(g + tid * 4);
    float4 bv = *(const float4*)(b + tid * 4);
    float4 o;
    o.x = (v4.x - mu) * inv * gv.x + bv.x;
    o.y = (v4.y - mu) * inv * gv.y + bv.y;
    o.z = (v4.z - mu) * inv * gv.z + bv.z;
    o.w = (v4.w - mu) * inv * gv.w + bv.w;
    *(float4*)(out + (size_t)row * DMODEL + tid * 4) = o;
}

// =====================================================================
// host launcher
// =====================================================================
extern "C" void kernel_launch(void* const* d_in, const int* in_sizes, int n_in,
                              void* d_out, int out_size)
{
    const int*   src  = (const int*)  d_in[0];
    const float* emb  = (const float*)d_in[1];
    const float* pe   = (const float*)d_in[2];
    const float* Wq   = (const float*)d_in[3];
    const float* bq   = (const float*)d_in[4];
    const float* Wk   = (const float*)d_in[5];
    const float* bk   = (const float*)d_in[6];
    const float* Wv   = (const float*)d_in[7];
    const float* bv   = (const float*)d_in[8];
    const float* Wo   = (const float*)d_in[9];
    const float* bo   = (const float*)d_in[10];
    const float* W1   = (const float*)d_in[11];
    const float* b1   = (const float*)d_in[12];
    const float* W2   = (const float*)d_in[13];
    const float* b2   = (const float*)d_in[14];
    const float* g1   = (const float*)d_in[15];
    const float* be1  = (const float*)d_in[16];
    const float* g2   = (const float*)d_in[17];
    const float* be2  = (const float*)d_in[18];
    float* outp = (float*)d_out;

    float *x, *q, *k, *v, *attn, *tmp, *ff;
    cudaGetSymbolAddress((void**)&x,    g_x);
    cudaGetSymbolAddress((void**)&q,    g_q);
    cudaGetSymbolAddress((void**)&k,    g_k);
    cudaGetSymbolAddress((void**)&v,    g_v);
    cudaGetSymbolAddress((void**)&attn, g_attn);
    cudaGetSymbolAddress((void**)&tmp,  g_tmp);
    cudaGetSymbolAddress((void**)&ff,   g_ff);

    cudaFuncSetAttribute(attn_kernel,
                         cudaFuncAttributeMaxDynamicSharedMemorySize, ATTN_SMEM);

    embed_kernel<<<MROWS, 128>>>(src, emb, pe, x);

    dim3 gProj(DMODEL / 128, MROWS / 128);   // (4, 64)
    dim3 gFF1(DFF / 128,    MROWS / 128);    // (16, 64)
    dim3 gAttn(SEQ / 64, BATCH * NHEADS);    // (32, 32)

    for (int L = 0; L < NLAYERS; L++) {
        const size_t wdd = (size_t)L * DMODEL * DMODEL;
        const size_t wdf = (size_t)L * DMODEL * DFF;
        const size_t vd  = (size_t)L * DMODEL;
        const size_t vf  = (size_t)L * DFF;

        gemm_kernel<<<gProj, 256>>>(x, Wq + wdd, bq + vd, nullptr, q,
                                    MROWS, DMODEL, DMODEL, 0);
        gemm_kernel<<<gProj, 256>>>(x, Wk + wdd, bk + vd, nullptr, k,
                                    MROWS, DMODEL, DMODEL, 0);
        gemm_kernel<<<gProj, 256>>>(x, Wv + wdd, bv + vd, nullptr, v,
                                    MROWS, DMODEL, DMODEL, 0);

        attn_kernel<<<gAttn, 256, ATTN_SMEM>>>(q, k, v, attn);

        // o-proj + residual, then LN1 -> x
        gemm_kernel<<<gProj, 256>>>(attn, Wo + wdd, bo + vd, x, tmp,
                                    MROWS, DMODEL, DMODEL, 0);
        ln_kernel<<<MROWS, 128>>>(tmp, g1 + vd, be1 + vd, x);

        // FF
        gemm_kernel<<<gFF1, 256>>>(x, W1 + wdf, b1 + vf, nullptr, ff,
                                   MROWS, DFF, DMODEL, 1);
        gemm_kernel<<<gProj, 256>>>(ff, W2 + wdf, b2 + vd, x, tmp,
                                    MROWS, DMODEL, DFF, 0);
        ln_kernel<<<MROWS, 128>>>(tmp, g2 + vd, be2 + vd,
                                  (L == NLAYERS - 1) ? outp : x);
    }
}

// round 4
// speedup vs baseline: 1.3839x; 1.3839x over previous
#include <cuda_runtime.h>
#include <cuda_bf16.h>
#include <cstdint>
#include <cstddef>

// Problem constants
#define BATCH   4
#define SEQ     2048
#define DMODEL  512
#define NHEADS  8
#define HDIM    64
#define DFF     2048
#define NLAYERS 6
#define MROWS   (BATCH * SEQ)            // 8192

// -------- scratch (device globals; no allocation allowed) --------
__device__ float g_x   [MROWS * DMODEL];
__device__ float g_q   [MROWS * DMODEL];
__device__ float g_k   [MROWS * DMODEL];
__device__ float g_v   [MROWS * DMODEL];
__device__ float g_attn[MROWS * DMODEL];
__device__ float g_tmp [MROWS * DMODEL];
__device__ float g_ff  [MROWS * DFF];

// ==================== helpers ====================
__device__ __forceinline__ uint32_t f2tf32(float x) {
    uint32_t u;
    asm("cvt.rna.tf32.f32 %0, %1;" : "=r"(u) : "f"(x));
    return u;
}

// mma.sync m16n8k8 tf32: d = a*b + c  (f32 accum)
__device__ __forceinline__ void mma_tf32(
    float* d, const uint32_t* a, const uint32_t* b, const float* c)
{
    asm volatile(
        "mma.sync.aligned.m16n8k8.row.col.f32.tf32.tf32.f32 "
        "{%0,%1,%2,%3}, {%4,%5,%6,%7}, {%8,%9}, {%10,%11,%12,%13};"
        : "=f"(d[0]), "=f"(d[1]), "=f"(d[2]), "=f"(d[3])
        : "r"(a[0]), "r"(a[1]), "r"(a[2]), "r"(a[3]),
          "r"(b[0]), "r"(b[1]),
          "f"(c[0]), "f"(c[1]), "f"(c[2]), "f"(c[3]));
}

// =====================================================================
// Embedding + positional encoding
// =====================================================================
__global__ void __launch_bounds__(128) embed_kernel(
    const int* __restrict__ src, const float* __restrict__ emb,
    const float* __restrict__ pe, float* __restrict__ x)
{
    int bl  = blockIdx.x;
    int l   = bl & (SEQ - 1);
    int tok = src[bl];
    int c   = threadIdx.x * 4;
    float4 e = *(const float4*)(emb + (size_t)tok * DMODEL + c);
    float4 p = *(const float4*)(pe  + (size_t)l   * DMODEL + c);
    float4 o; o.x = e.x + p.x; o.y = e.y + p.y; o.z = e.z + p.z; o.w = e.w + p.w;
    *(float4*)(x + (size_t)bl * DMODEL + c) = o;
}

// =====================================================================
// Tensor-core GEMM (tf32 mma.sync): C[M,N] = A[M,K] @ W[K,N] + bias
// (+ residual) (+relu).  W in natural [K][N] layout.
// CTA tile 128x128, 8 warps (2x4), warp tile 64x32 (4x4 m16n8k8 tiles).
// Smem stages of K=16, double buffered, k-major stride 132 (bank-clean).
// =====================================================================
#define KC   16
#define SST  132

__global__ void __launch_bounds__(256, 2) gemm_mma(
    const float* __restrict__ A, const float* __restrict__ W,
    const float* __restrict__ bias, const float* __restrict__ res,
    float* __restrict__ C, int M, int N, int K, int relu)
{
    __shared__ uint32_t As[2][KC][SST];
    __shared__ uint32_t Bs[2][KC][SST];

    int tid  = threadIdx.x;
    int lane = tid & 31;
    int wid  = tid >> 5;
    int bm = blockIdx.y << 7, bn = blockIdx.x << 7;
    int warpM = (wid >> 2) * 64;
    int warpN = (wid & 3) * 32;

    // loader mapping
    int lm  = tid >> 1;            // A row 0..127
    int lkh = (tid & 1) * 4;       // A k sub-offset {0,4}
    int lbk = tid >> 4;            // B k row 0..15
    int lbn = (tid & 15) * 4;      // B col group
    const float* Ag = A + (size_t)(bm + lm) * K + lkh;
    const float* Bg = W + (size_t)lbk * N + bn + lbn;

    float acc[4][4][4];
#pragma unroll
    for (int mt = 0; mt < 4; mt++)
#pragma unroll
        for (int nt = 0; nt < 4; nt++)
#pragma unroll
            for (int r = 0; r < 4; r++) acc[mt][nt][r] = 0.f;

    int nst = K / KC;

    // ---- preload stage 0 ----
    {
#pragma unroll
        for (int r = 0; r < 2; r++) {
            float4 v = *(const float4*)(Ag + r * 8);
            int kb = lkh + r * 8;
            As[0][kb + 0][lm] = f2tf32(v.x);
            As[0][kb + 1][lm] = f2tf32(v.y);
            As[0][kb + 2][lm] = f2tf32(v.z);
            As[0][kb + 3][lm] = f2tf32(v.w);
        }
#pragma unroll
        for (int p = 0; p < 2; p++) {
            float4 v = *(const float4*)(Bg + p * 64);
            uint4 u = make_uint4(f2tf32(v.x), f2tf32(v.y), f2tf32(v.z), f2tf32(v.w));
            *(uint4*)&Bs[0][lbk][lbn + p * 64] = u;
        }
    }
    __syncthreads();

    float4 stA[2], stB[2];
    for (int s = 0; s < nst; s++) {
        int cur = s & 1;
        if (s + 1 < nst) {
            int kc = (s + 1) * KC;
            stA[0] = *(const float4*)(Ag + kc);
            stA[1] = *(const float4*)(Ag + kc + 8);
            stB[0] = *(const float4*)(Bg + (size_t)kc * N);
            stB[1] = *(const float4*)(Bg + (size_t)kc * N + 64);
        }
        // ---- compute: 2 k-steps of 8 ----
#pragma unroll
        for (int ks = 0; ks < 2; ks++) {
            int k0 = ks * 8 + (lane & 3);
            uint32_t a[4][4], b[4][2];
#pragma unroll
            for (int mt = 0; mt < 4; mt++) {
                int m0 = warpM + mt * 16 + (lane >> 2);
                a[mt][0] = As[cur][k0][m0];
                a[mt][1] = As[cur][k0][m0 + 8];
                a[mt][2] = As[cur][k0 + 4][m0];
                a[mt][3] = As[cur][k0 + 4][m0 + 8];
            }
#pragma unroll
            for (int nt = 0; nt < 4; nt++) {
                int n0 = warpN + nt * 8 + (lane >> 2);
                b[nt][0] = Bs[cur][k0][n0];
                b[nt][1] = Bs[cur][k0 + 4][n0];
            }
#pragma unroll
            for (int mt = 0; mt < 4; mt++)
#pragma unroll
                for (int nt = 0; nt < 4; nt++)
                    mma_tf32(acc[mt][nt], a[mt], b[nt], acc[mt][nt]);
        }
        if (s + 1 < nst) {
            int nb = cur ^ 1;
#pragma unroll
            for (int r = 0; r < 2; r++) {
                float4 v = stA[r];
                int kb = lkh + r * 8;
                As[nb][kb + 0][lm] = f2tf32(v.x);
                As[nb][kb + 1][lm] = f2tf32(v.y);
                As[nb][kb + 2][lm] = f2tf32(v.z);
                As[nb][kb + 3][lm] = f2tf32(v.w);
            }
#pragma unroll
            for (int p = 0; p < 2; p++) {
                float4 v = stB[p];
                uint4 u = make_uint4(f2tf32(v.x), f2tf32(v.y), f2tf32(v.z), f2tf32(v.w));
                *(uint4*)&Bs[nb][lbk][lbn + p * 64] = u;
            }
            __syncthreads();
        }
    }

    // ---- epilogue ----
#pragma unroll
    for (int mt = 0; mt < 4; mt++) {
        int row0 = bm + warpM + mt * 16 + (lane >> 2);
#pragma unroll
        for (int h = 0; h < 2; h++) {
            int row = row0 + h * 8;
            float* crow = C + (size_t)row * N;
            const float* rrow = res ? (res + (size_t)row * N) : nullptr;
#pragma unroll
            for (int nt = 0; nt < 4; nt++) {
                int col = bn + warpN + nt * 8 + (lane & 3) * 2;
                float2 b2 = *(const float2*)(bias + col);
                float2 o;
                o.x = acc[mt][nt][h * 2 + 0] + b2.x;
                o.y = acc[mt][nt][h * 2 + 1] + b2.y;
                if (rrow) {
                    float2 r2 = *(const float2*)(rrow + col);
                    o.x += r2.x; o.y += r2.y;
                }
                if (relu) { o.x = fmaxf(o.x, 0.f); o.y = fmaxf(o.y, 0.f); }
                *(float2*)(crow + col) = o;
            }
        }
    }
}

// =====================================================================
// Flash attention (SIMT fp32, round-2 known-good)
// =====================================================================
#define AST 68
#define ATTN_SMEM (4 * 64 * AST * 4)

__global__ void __launch_bounds__(256) attn_kernel(
    const float* __restrict__ q, const float* __restrict__ k,
    const float* __restrict__ v, float* __restrict__ out)
{
    extern __shared__ float sm[];
    float* Qs = sm;
    float* Ks = Qs + 64 * AST;
    float* Vs = Ks + 64 * AST;
    float* Ss = Vs + 64 * AST;

    int tid = threadIdx.x;
    int tx  = tid & 15;
    int ty  = tid >> 4;
    int bh  = blockIdx.y;
    int qt  = blockIdx.x;
    int b   = bh >> 3, h = bh & 7;

    const float* Qg = q + ((size_t)bh * SEQ + qt * 64) * HDIM;
    const float* Kg = k + (size_t)bh * SEQ * HDIM;
    const float* Vg = v + (size_t)bh * SEQ * HDIM;
    float* Og = out + ((size_t)b * SEQ + qt * 64) * DMODEL + h * HDIM;

    {
        int c = (tid & 15) * 4;
#pragma unroll
        for (int r = 0; r < 4; r++) {
            int row = (tid >> 4) + r * 16;
            *(float4*)(Qs + row * AST + c) = *(const float4*)(Qg + row * 64 + c);
        }
    }

    float m_i[4], l_i[4], o_acc[4][4];
#pragma unroll
    for (int i = 0; i < 4; i++) {
        m_i[i] = -1e30f; l_i[i] = 0.f;
#pragma unroll
        for (int j = 0; j < 4; j++) o_acc[i][j] = 0.f;
    }

    for (int kt = 0; kt < SEQ / 64; kt++) {
        __syncthreads();
        {
            int c = (tid & 15) * 4;
#pragma unroll
            for (int r = 0; r < 4; r++) {
                int row = (tid >> 4) + r * 16;
                *(float4*)(Ks + row * AST + c) =
                    *(const float4*)(Kg + (size_t)(kt * 64 + row) * 64 + c);
                *(float4*)(Vs + row * AST + c) =
                    *(const float4*)(Vg + (size_t)(kt * 64 + row) * 64 + c);
            }
        }
        __syncthreads();

        float s[4][4];
#pragma unroll
        for (int i = 0; i < 4; i++)
#pragma unroll
            for (int j = 0; j < 4; j++) s[i][j] = 0.f;

#pragma unroll
        for (int kc = 0; kc < 16; kc++) {
            float4 a[4], bb[4];
#pragma unroll
            for (int i = 0; i < 4; i++)
                a[i] = *(const float4*)(Qs + (ty * 4 + i) * AST + kc * 4);
#pragma unroll
            for (int j = 0; j < 4; j++)
                bb[j] = *(const float4*)(Ks + (tx + 16 * j) * AST + kc * 4);
#pragma unroll
            for (int i = 0; i < 4; i++)
#pragma unroll
                for (int j = 0; j < 4; j++)
                    s[i][j] += a[i].x * bb[j].x + a[i].y * bb[j].y +
                               a[i].z * bb[j].z + a[i].w * bb[j].w;
        }
#pragma unroll
        for (int i = 0; i < 4; i++)
#pragma unroll
            for (int j = 0; j < 4; j++) s[i][j] *= 0.125f;

        float corr[4];
#pragma unroll
        for (int i = 0; i < 4; i++) {
            float mt = fmaxf(fmaxf(s[i][0], s[i][1]), fmaxf(s[i][2], s[i][3]));
#pragma unroll
            for (int off = 1; off < 16; off <<= 1)
                mt = fmaxf(mt, __shfl_xor_sync(0xffffffffu, mt, off, 16));
            float m_new = fmaxf(m_i[i], mt);
            corr[i] = __expf(m_i[i] - m_new);
            float rs = 0.f;
#pragma unroll
            for (int j = 0; j < 4; j++) {
                float p = __expf(s[i][j] - m_new);
                s[i][j] = p;
                rs += p;
            }
#pragma unroll
            for (int off = 1; off < 16; off <<= 1)
                rs += __shfl_xor_sync(0xffffffffu, rs, off, 16);
            l_i[i] = l_i[i] * corr[i] + rs;
            m_i[i] = m_new;
#pragma unroll
            for (int j = 0; j < 4; j++) o_acc[i][j] *= corr[i];
        }

#pragma unroll
        for (int i = 0; i < 4; i++)
#pragma unroll
            for (int j = 0; j < 4; j++)
                Ss[(ty * 4 + i) * AST + tx + 16 * j] = s[i][j];
        __syncthreads();

#pragma unroll
        for (int kc = 0; kc < 16; kc++) {
            float4 a[4];
#pragma unroll
            for (int i = 0; i < 4; i++)
                a[i] = *(const float4*)(Ss + (ty * 4 + i) * AST + kc * 4);
#pragma unroll
            for (int t = 0; t < 4; t++) {
                float4 bv = *(const float4*)(Vs + (kc * 4 + t) * AST + tx * 4);
#pragma unroll
                for (int i = 0; i < 4; i++) {
                    float av = ((const float*)&a[i])[t];
                    o_acc[i][0] += av * bv.x;
                    o_acc[i][1] += av * bv.y;
                    o_acc[i][2] += av * bv.z;
                    o_acc[i][3] += av * bv.w;
                }
            }
        }
    }

#pragma unroll
    for (int i = 0; i < 4; i++) {
        float inv = 1.0f / l_i[i];
        float4 o;
        o.x = o_acc[i][0] * inv; o.y = o_acc[i][1] * inv;
        o.z = o_acc[i][2] * inv; o.w = o_acc[i][3] * inv;
        *(float4*)(Og + (size_t)(ty * 4 + i) * DMODEL + tx * 4) = o;
    }
}

// =====================================================================
// LayerNorm over last dim (512). Block per row, 128 threads.
// =====================================================================
__global__ void __launch_bounds__(128) ln_kernel(
    const float* __restrict__ in, const float* __restrict__ g,
    const float* __restrict__ b, float* __restrict__ out)
{
    int row = blockIdx.x;
    int tid = threadIdx.x;
    float4 v4 = *(const float4*)(in + (size_t)row * DMODEL + tid * 4);
    float s  = v4.x + v4.y + v4.z + v4.w;
    float sq = v4.x * v4.x + v4.y * v4.y + v4.z * v4.z + v4.w * v4.w;
#pragma unroll
    for (int off = 16; off > 0; off >>= 1) {
        s  += __shfl_xor_sync(0xffffffffu, s, off);
        sq += __shfl_xor_sync(0xffffffffu, sq, off);
    }
    __shared__ float ss[4], sqs[4];
    int wid = tid >> 5;
    if ((tid & 31) == 0) { ss[wid] = s; sqs[wid] = sq; }
    __syncthreads();
    s  = ss[0] + ss[1] + ss[2] + ss[3];
    sq = sqs[0] + sqs[1] + sqs[2] + sqs[3];
    float mu  = s * (1.0f / DMODEL);
    float var = sq * (1.0f / DMODEL) - mu * mu;
    float inv = rsqrtf(var + 1e-5f);
    float4 gv = *(const float4*)(g + tid * 4);
    float4 bv = *(const float4*)(b + tid * 4);
    float4 o;
    o.x = (v4.x - mu) * inv * gv.x + bv.x;
    o.y = (v4.y - mu) * inv * gv.y + bv.y;
    o.z = (v4.z - mu) * inv * gv.z + bv.z;
    o.w = (v4.w - mu) * inv * gv.w + bv.w;
    *(float4*)(out + (size_t)row * DMODEL + tid * 4) = o;
}

// =====================================================================
// host launcher
// =====================================================================
extern "C" void kernel_launch(void* const* d_in, const int* in_sizes, int n_in,
                              void* d_out, int out_size)
{
    const int*   src  = (const int*)  d_in[0];
    const float* emb  = (const float*)d_in[1];
    const float* pe   = (const float*)d_in[2];
    const float* Wq   = (const float*)d_in[3];
    const float* bq   = (const float*)d_in[4];
    const float* Wk   = (const float*)d_in[5];
    const float* bk   = (const float*)d_in[6];
    const float* Wv   = (const float*)d_in[7];
    const float* bv   = (const float*)d_in[8];
    const float* Wo   = (const float*)d_in[9];
    const float* bo   = (const float*)d_in[10];
    const float* W1   = (const float*)d_in[11];
    const float* b1   = (const float*)d_in[12];
    const float* W2   = (const float*)d_in[13];
    const float* b2   = (const float*)d_in[14];
    const float* g1   = (const float*)d_in[15];
    const float* be1  = (const float*)d_in[16];
    const float* g2   = (const float*)d_in[17];
    const float* be2  = (const float*)d_in[18];
    float* outp = (float*)d_out;

    float *x, *q, *k, *v, *attn, *tmp, *ff;
    cudaGetSymbolAddress((void**)&x,    g_x);
    cudaGetSymbolAddress((void**)&q,    g_q);
    cudaGetSymbolAddress((void**)&k,    g_k);
    cudaGetSymbolAddress((void**)&v,    g_v);
    cudaGetSymbolAddress((void**)&attn, g_attn);
    cudaGetSymbolAddress((void**)&tmp,  g_tmp);
    cudaGetSymbolAddress((void**)&ff,   g_ff);

    cudaFuncSetAttribute(attn_kernel,
                         cudaFuncAttributeMaxDynamicSharedMemorySize, ATTN_SMEM);

    embed_kernel<<<MROWS, 128>>>(src, emb, pe, x);

    dim3 gProj(DMODEL / 128, MROWS / 128);   // (4, 64)
    dim3 gFF1(DFF / 128,    MROWS / 128);    // (16, 64)
    dim3 gAttn(SEQ / 64, BATCH * NHEADS);    // (32, 32)

    for (int L = 0; L < NLAYERS; L++) {
        const size_t wdd = (size_t)L * DMODEL * DMODEL;
        const size_t wdf = (size_t)L * DMODEL * DFF;
        const size_t vd  = (size_t)L * DMODEL;
        const size_t vf  = (size_t)L * DFF;

        gemm_mma<<<gProj, 256>>>(x, Wq + wdd, bq + vd, nullptr, q,
                                 MROWS, DMODEL, DMODEL, 0);
        gemm_mma<<<gProj, 256>>>(x, Wk + wdd, bk + vd, nullptr, k,
                                 MROWS, DMODEL, DMODEL, 0);
        gemm_mma<<<gProj, 256>>>(x, Wv + wdd, bv + vd, nullptr, v,
                                 MROWS, DMODEL, DMODEL, 0);

        attn_kernel<<<gAttn, 256, ATTN_SMEM>>>(q, k, v, attn);

        gemm_mma<<<gProj, 256>>>(attn, Wo + wdd, bo + vd, x, tmp,
                                 MROWS, DMODEL, DMODEL, 0);
        ln_kernel<<<MROWS, 128>>>(tmp, g1 + vd, be1 + vd, x);

        gemm_mma<<<gFF1, 256>>>(x, W1 + wdf, b1 + vf, nullptr, ff,
                                MROWS, DFF, DMODEL, 1);
        gemm_mma<<<gProj, 256>>>(ff, W2 + wdf, b2 + vd, x, tmp,
                                 MROWS, DMODEL, DFF, 0);
        ln_kernel<<<MROWS, 128>>>(tmp, g2 + vd, be2 + vd,
                                  (L == NLAYERS - 1) ? outp : x);
    }
}

// round 5
// speedup vs baseline: 2.2101x; 1.5970x over previous
#include <cuda_runtime.h>
#include <cuda_bf16.h>
#include <cstdint>
#include <cstddef>

// Problem constants
#define BATCH   4
#define SEQ     2048
#define DMODEL  512
#define NHEADS  8
#define HDIM    64
#define DFF     2048
#define NLAYERS 6
#define MROWS   (BATCH * SEQ)            // 8192

// -------- scratch (device globals; no allocation allowed) --------
__device__ float g_x   [MROWS * DMODEL];
__device__ float g_q   [MROWS * DMODEL];
__device__ float g_k   [MROWS * DMODEL];
__device__ float g_v   [MROWS * DMODEL];
__device__ float g_attn[MROWS * DMODEL];
__device__ float g_tmp [MROWS * DMODEL];
__device__ float g_ff  [MROWS * DFF];

// ==================== helpers ====================
__device__ __forceinline__ uint32_t f2tf32(float x) {
    uint32_t u;
    asm("cvt.rna.tf32.f32 %0, %1;" : "=r"(u) : "f"(x));
    return u;
}

// mma.sync m16n8k8 tf32: d = a*b + c  (f32 accum)
// a frag: a0=(r,k) a1=(r+8,k) a2=(r,k+4) a3=(r+8,k+4), r=lane>>2, k=lane&3
// b frag: b0=(k=lane&3, n=lane>>2) b1=(k+4, n)
// c frag: c0=(r,2c) c1=(r,2c+1) c2=(r+8,2c) c3=(r+8,2c+1), c=lane&3
__device__ __forceinline__ void mma_tf32(
    float* d, const uint32_t* a, const uint32_t* b, const float* c)
{
    asm volatile(
        "mma.sync.aligned.m16n8k8.row.col.f32.tf32.tf32.f32 "
        "{%0,%1,%2,%3}, {%4,%5,%6,%7}, {%8,%9}, {%10,%11,%12,%13};"
        : "=f"(d[0]), "=f"(d[1]), "=f"(d[2]), "=f"(d[3])
        : "r"(a[0]), "r"(a[1]), "r"(a[2]), "r"(a[3]),
          "r"(b[0]), "r"(b[1]),
          "f"(c[0]), "f"(c[1]), "f"(c[2]), "f"(c[3]));
}

// =====================================================================
// Embedding + positional encoding
// =====================================================================
__global__ void __launch_bounds__(128) embed_kernel(
    const int* __restrict__ src, const float* __restrict__ emb,
    const float* __restrict__ pe, float* __restrict__ x)
{
    int bl  = blockIdx.x;
    int l   = bl & (SEQ - 1);
    int tok = src[bl];
    int c   = threadIdx.x * 4;
    float4 e = *(const float4*)(emb + (size_t)tok * DMODEL + c);
    float4 p = *(const float4*)(pe  + (size_t)l   * DMODEL + c);
    float4 o; o.x = e.x + p.x; o.y = e.y + p.y; o.z = e.z + p.z; o.w = e.w + p.w;
    *(float4*)(x + (size_t)bl * DMODEL + c) = o;
}

// =====================================================================
// Tensor-core GEMM body (tf32 mma.sync): C = A@W + bias (+res)(+relu)
// CTA 128x128, 8 warps (2x4), warp tile 64x32. K stages of 16, dbuf.
// =====================================================================
#define KC   16
#define SST  132

__device__ __forceinline__ void gemm_body(
    const float* __restrict__ A, const float* __restrict__ W,
    const float* __restrict__ bias, const float* __restrict__ res,
    float* __restrict__ C, int M, int N, int K, int relu,
    int bxx, int byy)
{
    __shared__ uint32_t As[2][KC][SST];
    __shared__ uint32_t Bs[2][KC][SST];

    int tid  = threadIdx.x;
    int lane = tid & 31;
    int wid  = tid >> 5;
    int bm = byy << 7, bn = bxx << 7;
    int warpM = (wid >> 2) * 64;
    int warpN = (wid & 3) * 32;

    int lm  = tid >> 1;
    int lkh = (tid & 1) * 4;
    int lbk = tid >> 4;
    int lbn = (tid & 15) * 4;
    const float* Ag = A + (size_t)(bm + lm) * K + lkh;
    const float* Bg = W + (size_t)lbk * N + bn + lbn;

    float acc[4][4][4];
#pragma unroll
    for (int mt = 0; mt < 4; mt++)
#pragma unroll
        for (int nt = 0; nt < 4; nt++)
#pragma unroll
            for (int r = 0; r < 4; r++) acc[mt][nt][r] = 0.f;

    int nst = K / KC;
    {
#pragma unroll
        for (int r = 0; r < 2; r++) {
            float4 v = *(const float4*)(Ag + r * 8);
            int kb = lkh + r * 8;
            As[0][kb + 0][lm] = f2tf32(v.x);
            As[0][kb + 1][lm] = f2tf32(v.y);
            As[0][kb + 2][lm] = f2tf32(v.z);
            As[0][kb + 3][lm] = f2tf32(v.w);
        }
#pragma unroll
        for (int p = 0; p < 2; p++) {
            float4 v = *(const float4*)(Bg + p * 64);
            uint4 u = make_uint4(f2tf32(v.x), f2tf32(v.y), f2tf32(v.z), f2tf32(v.w));
            *(uint4*)&Bs[0][lbk][lbn + p * 64] = u;
        }
    }
    __syncthreads();

    float4 stA[2], stB[2];
    for (int s = 0; s < nst; s++) {
        int cur = s & 1;
        if (s + 1 < nst) {
            int kc = (s + 1) * KC;
            stA[0] = *(const float4*)(Ag + kc);
            stA[1] = *(const float4*)(Ag + kc + 8);
            stB[0] = *(const float4*)(Bg + (size_t)kc * N);
            stB[1] = *(const float4*)(Bg + (size_t)kc * N + 64);
        }
#pragma unroll
        for (int ks = 0; ks < 2; ks++) {
            int k0 = ks * 8 + (lane & 3);
            uint32_t a[4][4], b[4][2];
#pragma unroll
            for (int mt = 0; mt < 4; mt++) {
                int m0 = warpM + mt * 16 + (lane >> 2);
                a[mt][0] = As[cur][k0][m0];
                a[mt][1] = As[cur][k0][m0 + 8];
                a[mt][2] = As[cur][k0 + 4][m0];
                a[mt][3] = As[cur][k0 + 4][m0 + 8];
            }
#pragma unroll
            for (int nt = 0; nt < 4; nt++) {
                int n0 = warpN + nt * 8 + (lane >> 2);
                b[nt][0] = Bs[cur][k0][n0];
                b[nt][1] = Bs[cur][k0 + 4][n0];
            }
#pragma unroll
            for (int mt = 0; mt < 4; mt++)
#pragma unroll
                for (int nt = 0; nt < 4; nt++)
                    mma_tf32(acc[mt][nt], a[mt], b[nt], acc[mt][nt]);
        }
        if (s + 1 < nst) {
            int nb = cur ^ 1;
#pragma unroll
            for (int r = 0; r < 2; r++) {
                float4 v = stA[r];
                int kb = lkh + r * 8;
                As[nb][kb + 0][lm] = f2tf32(v.x);
                As[nb][kb + 1][lm] = f2tf32(v.y);
                As[nb][kb + 2][lm] = f2tf32(v.z);
                As[nb][kb + 3][lm] = f2tf32(v.w);
            }
#pragma unroll
            for (int p = 0; p < 2; p++) {
                float4 v = stB[p];
                uint4 u = make_uint4(f2tf32(v.x), f2tf32(v.y), f2tf32(v.z), f2tf32(v.w));
                *(uint4*)&Bs[nb][lbk][lbn + p * 64] = u;
            }
            __syncthreads();
        }
    }

#pragma unroll
    for (int mt = 0; mt < 4; mt++) {
        int row0 = bm + warpM + mt * 16 + (lane >> 2);
#pragma unroll
        for (int h = 0; h < 2; h++) {
            int row = row0 + h * 8;
            float* crow = C + (size_t)row * N;
            const float* rrow = res ? (res + (size_t)row * N) : nullptr;
#pragma unroll
            for (int nt = 0; nt < 4; nt++) {
                int col = bn + warpN + nt * 8 + (lane & 3) * 2;
                float2 b2 = *(const float2*)(bias + col);
                float2 o;
                o.x = acc[mt][nt][h * 2 + 0] + b2.x;
                o.y = acc[mt][nt][h * 2 + 1] + b2.y;
                if (rrow) {
                    float2 r2 = *(const float2*)(rrow + col);
                    o.x += r2.x; o.y += r2.y;
                }
                if (relu) { o.x = fmaxf(o.x, 0.f); o.y = fmaxf(o.y, 0.f); }
                *(float2*)(crow + col) = o;
            }
        }
    }
}

__global__ void __launch_bounds__(256, 2) gemm_mma(
    const float* __restrict__ A, const float* __restrict__ W,
    const float* __restrict__ bias, const float* __restrict__ res,
    float* __restrict__ C, int M, int N, int K, int relu)
{
    gemm_body(A, W, bias, res, C, M, N, K, relu, blockIdx.x, blockIdx.y);
}

// fused QKV: blockIdx.z selects {Wq,bq,q} / {Wk,bk,k} / {Wv,bv,v}
__global__ void __launch_bounds__(256, 2) gemm_qkv(
    const float* __restrict__ x,
    const float* __restrict__ Wq, const float* __restrict__ Wk,
    const float* __restrict__ Wv,
    const float* __restrict__ bq, const float* __restrict__ bk,
    const float* __restrict__ bv,
    float* __restrict__ q, float* __restrict__ k, float* __restrict__ v)
{
    const float* W; const float* bias; float* C;
    if (blockIdx.z == 0)      { W = Wq; bias = bq; C = q; }
    else if (blockIdx.z == 1) { W = Wk; bias = bk; C = k; }
    else                      { W = Wv; bias = bv; C = v; }
    gemm_body(x, W, bias, nullptr, C, MROWS, DMODEL, DMODEL, 0,
              blockIdx.x, blockIdx.y);
}

// =====================================================================
// Tensor-core flash attention (tf32 mma.sync).
// Heads = contiguous [2048,64] slabs. grid=(32 qtiles, 32 b*h), 128 thr.
// 4 warps, warp owns 16 query rows. K/V tiles 64x64. Online softmax in
// mma C-fragments; P -> smem (tf32, warp-private rows) -> A-fragments.
// Output scattered to [B, L, H*64].
// =====================================================================
#define ATS 68
#define ATTN2_SMEM (4 * 64 * ATS * 4)

// load 64x64 fp32 tile (row stride 64) -> smem tf32 (stride ATS)
__device__ __forceinline__ void load_tile_tf32(
    const float* __restrict__ g, uint32_t* __restrict__ s, int tid)
{
#pragma unroll
    for (int p = 0; p < 8; p++) {
        int idx = (tid + p * 128) * 4;     // element index, fully coalesced
        int row = idx >> 6, col = idx & 63;
        float4 v = *(const float4*)(g + idx);
        uint32_t* d = s + row * ATS + col;
        d[0] = f2tf32(v.x); d[1] = f2tf32(v.y);
        d[2] = f2tf32(v.z); d[3] = f2tf32(v.w);
    }
}

__global__ void __launch_bounds__(128, 2) attn_mma(
    const float* __restrict__ q, const float* __restrict__ k,
    const float* __restrict__ v, float* __restrict__ out)
{
    extern __shared__ uint32_t smu[];
    uint32_t* Qs = smu;
    uint32_t* Ks = Qs + 64 * ATS;
    uint32_t* Vs = Ks + 64 * ATS;
    uint32_t* Ps = Vs + 64 * ATS;

    int tid  = threadIdx.x;
    int lane = tid & 31;
    int wid  = tid >> 5;
    int bh   = blockIdx.y;
    int qt   = blockIdx.x;
    int b    = bh >> 3, h = bh & 7;

    const float* Qg = q + ((size_t)bh * SEQ + qt * 64) * HDIM;
    const float* Kg = k + (size_t)bh * SEQ * HDIM;
    const float* Vg = v + (size_t)bh * SEQ * HDIM;

    load_tile_tf32(Qg, Qs, tid);

    int warpM = wid * 16;
    int r0 = lane >> 2, c0 = lane & 3;

    float m0 = -1e30f, m1 = -1e30f, l0 = 0.f, l1 = 0.f;
    float o_acc[8][4];
#pragma unroll
    for (int nt = 0; nt < 8; nt++)
#pragma unroll
        for (int r = 0; r < 4; r++) o_acc[nt][r] = 0.f;

    for (int kt = 0; kt < SEQ / 64; kt++) {
        __syncthreads();                 // Ks/Vs free; Qs visible on kt=0
        load_tile_tf32(Kg + (size_t)kt * 64 * HDIM, Ks, tid);
        load_tile_tf32(Vg + (size_t)kt * 64 * HDIM, Vs, tid);
        __syncthreads();

        // ---- S = Q K^T (M=64 rows, N=64 keys, K=64 dims) ----
        float sacc[8][4];
#pragma unroll
        for (int nt = 0; nt < 8; nt++)
#pragma unroll
            for (int r = 0; r < 4; r++) sacc[nt][r] = 0.f;

#pragma unroll
        for (int ks = 0; ks < 8; ks++) {
            int kk = ks * 8 + c0;
            uint32_t a[4];
            a[0] = Qs[(warpM + r0) * ATS + kk];
            a[1] = Qs[(warpM + r0 + 8) * ATS + kk];
            a[2] = Qs[(warpM + r0) * ATS + kk + 4];
            a[3] = Qs[(warpM + r0 + 8) * ATS + kk + 4];
#pragma unroll
            for (int nt = 0; nt < 8; nt++) {
                uint32_t bb[2];
                bb[0] = Ks[(nt * 8 + r0) * ATS + kk];
                bb[1] = Ks[(nt * 8 + r0) * ATS + kk + 4];
                mma_tf32(sacc[nt], a, bb, sacc[nt]);
            }
        }

        // ---- online softmax (rows r0, r0+8 within warp tile) ----
        float mt0 = -1e30f, mt1 = -1e30f;
#pragma unroll
        for (int nt = 0; nt < 8; nt++) {
#pragma unroll
            for (int r = 0; r < 4; r++) sacc[nt][r] *= 0.125f;
            mt0 = fmaxf(mt0, fmaxf(sacc[nt][0], sacc[nt][1]));
            mt1 = fmaxf(mt1, fmaxf(sacc[nt][2], sacc[nt][3]));
        }
        mt0 = fmaxf(mt0, __shfl_xor_sync(0xffffffffu, mt0, 1));
        mt0 = fmaxf(mt0, __shfl_xor_sync(0xffffffffu, mt0, 2));
        mt1 = fmaxf(mt1, __shfl_xor_sync(0xffffffffu, mt1, 1));
        mt1 = fmaxf(mt1, __shfl_xor_sync(0xffffffffu, mt1, 2));

        float mn0 = fmaxf(m0, mt0), mn1 = fmaxf(m1, mt1);
        float corr0 = __expf(m0 - mn0), corr1 = __expf(m1 - mn1);
        m0 = mn0; m1 = mn1;

        float rs0 = 0.f, rs1 = 0.f;
#pragma unroll
        for (int nt = 0; nt < 8; nt++) {
            float p00 = __expf(sacc[nt][0] - mn0);
            float p01 = __expf(sacc[nt][1] - mn0);
            float p10 = __expf(sacc[nt][2] - mn1);
            float p11 = __expf(sacc[nt][3] - mn1);
            rs0 += p00 + p01; rs1 += p10 + p11;
            // store P tf32 (warp-private rows)
            uint2 u0 = make_uint2(f2tf32(p00), f2tf32(p01));
            uint2 u1 = make_uint2(f2tf32(p10), f2tf32(p11));
            *(uint2*)&Ps[(warpM + r0) * ATS + nt * 8 + 2 * c0] = u0;
            *(uint2*)&Ps[(warpM + r0 + 8) * ATS + nt * 8 + 2 * c0] = u1;
        }
        rs0 += __shfl_xor_sync(0xffffffffu, rs0, 1);
        rs0 += __shfl_xor_sync(0xffffffffu, rs0, 2);
        rs1 += __shfl_xor_sync(0xffffffffu, rs1, 1);
        rs1 += __shfl_xor_sync(0xffffffffu, rs1, 2);
        l0 = l0 * corr0 + rs0;
        l1 = l1 * corr1 + rs1;

#pragma unroll
        for (int nt = 0; nt < 8; nt++) {
            o_acc[nt][0] *= corr0; o_acc[nt][1] *= corr0;
            o_acc[nt][2] *= corr1; o_acc[nt][3] *= corr1;
        }
        __syncwarp();

        // ---- O += P @ V (M=64 rows, N=64 dims, K=64 keys) ----
#pragma unroll
        for (int ks = 0; ks < 8; ks++) {
            int kk = ks * 8;
            uint32_t a[4];
            a[0] = Ps[(warpM + r0) * ATS + kk + c0];
            a[1] = Ps[(warpM + r0 + 8) * ATS + kk + c0];
            a[2] = Ps[(warpM + r0) * ATS + kk + c0 + 4];
            a[3] = Ps[(warpM + r0 + 8) * ATS + kk + c0 + 4];
#pragma unroll
            for (int nt = 0; nt < 8; nt++) {
                uint32_t bb[2];
                bb[0] = Vs[(kk + c0) * ATS + nt * 8 + r0];
                bb[1] = Vs[(kk + c0 + 4) * ATS + nt * 8 + r0];
                mma_tf32(o_acc[nt], a, bb, o_acc[nt]);
            }
        }
    }

    // ---- epilogue: /l, scatter to [B, L, H*64 + d] ----
    float inv0 = 1.0f / l0, inv1 = 1.0f / l1;
    size_t row0 = (size_t)b * SEQ + qt * 64 + warpM + r0;
    float* O0 = out + row0 * DMODEL + h * HDIM;
    float* O1 = O0 + 8 * DMODEL;
#pragma unroll
    for (int nt = 0; nt < 8; nt++) {
        int col = nt * 8 + 2 * c0;
        float2 a = make_float2(o_acc[nt][0] * inv0, o_acc[nt][1] * inv0);
        float2 c = make_float2(o_acc[nt][2] * inv1, o_acc[nt][3] * inv1);
        *(float2*)(O0 + col) = a;
        *(float2*)(O1 + col) = c;
    }
}

// =====================================================================
// LayerNorm over last dim (512). Block per row, 128 threads.
// =====================================================================
__global__ void __launch_bounds__(128) ln_kernel(
    const float* __restrict__ in, const float* __restrict__ g,
    const float* __restrict__ b, float* __restrict__ out)
{
    int row = blockIdx.x;
    int tid = threadIdx.x;
    float4 v4 = *(const float4*)(in + (size_t)row * DMODEL + tid * 4);
    float s  = v4.x + v4.y + v4.z + v4.w;
    float sq = v4.x * v4.x + v4.y * v4.y + v4.z * v4.z + v4.w * v4.w;
#pragma unroll
    for (int off = 16; off > 0; off >>= 1) {
        s  += __shfl_xor_sync(0xffffffffu, s, off);
        sq += __shfl_xor_sync(0xffffffffu, sq, off);
    }
    __shared__ float ss[4], sqs[4];
    int wid = tid >> 5;
    if ((tid & 31) == 0) { ss[wid] = s; sqs[wid] = sq; }
    __syncthreads();
    s  = ss[0] + ss[1] + ss[2] + ss[3];
    sq = sqs[0] + sqs[1] + sqs[2] + sqs[3];
    float mu  = s * (1.0f / DMODEL);
    float var = sq * (1.0f / DMODEL) - mu * mu;
    float inv = rsqrtf(var + 1e-5f);
    float4 gv = *(const float4*)(g + tid * 4);
    float4 bv = *(const float4*)(b + tid * 4);
    float4 o;
    o.x = (v4.x - mu) * inv * gv.x + bv.x;
    o.y = (v4.y - mu) * inv * gv.y + bv.y;
    o.z = (v4.z - mu) * inv * gv.z + bv.z;
    o.w = (v4.w - mu) * inv * gv.w + bv.w;
    *(float4*)(out + (size_t)row * DMODEL + tid * 4) = o;
}

// =====================================================================
// host launcher
// =====================================================================
extern "C" void kernel_launch(void* const* d_in, const int* in_sizes, int n_in,
                              void* d_out, int out_size)
{
    const int*   src  = (const int*)  d_in[0];
    const float* emb  = (const float*)d_in[1];
    const float* pe   = (const float*)d_in[2];
    const float* Wq   = (const float*)d_in[3];
    const float* bq   = (const float*)d_in[4];
    const float* Wk   = (const float*)d_in[5];
    const float* bk   = (const float*)d_in[6];
    const float* Wv   = (const float*)d_in[7];
    const float* bv   = (const float*)d_in[8];
    const float* Wo   = (const float*)d_in[9];
    const float* bo   = (const float*)d_in[10];
    const float* W1   = (const float*)d_in[11];
    const float* b1   = (const float*)d_in[12];
    const float* W2   = (const float*)d_in[13];
    const float* b2   = (const float*)d_in[14];
    const float* g1   = (const float*)d_in[15];
    const float* be1  = (const float*)d_in[16];
    const float* g2   = (const float*)d_in[17];
    const float* be2  = (const float*)d_in[18];
    float* outp = (float*)d_out;

    float *x, *q, *k, *v, *attn, *tmp, *ff;
    cudaGetSymbolAddress((void**)&x,    g_x);
    cudaGetSymbolAddress((void**)&q,    g_q);
    cudaGetSymbolAddress((void**)&k,    g_k);
    cudaGetSymbolAddress((void**)&v,    g_v);
    cudaGetSymbolAddress((void**)&attn, g_attn);
    cudaGetSymbolAddress((void**)&tmp,  g_tmp);
    cudaGetSymbolAddress((void**)&ff,   g_ff);

    cudaFuncSetAttribute(attn_mma,
                         cudaFuncAttributeMaxDynamicSharedMemorySize, ATTN2_SMEM);

    embed_kernel<<<MROWS, 128>>>(src, emb, pe, x);

    dim3 gQKV(DMODEL / 128, MROWS / 128, 3);  // (4, 64, 3)
    dim3 gProj(DMODEL / 128, MROWS / 128);    // (4, 64)
    dim3 gFF1(DFF / 128,    MROWS / 128);     // (16, 64)
    dim3 gAttn(SEQ / 64, BATCH * NHEADS);     // (32, 32)

    for (int L = 0; L < NLAYERS; L++) {
        const size_t wdd = (size_t)L * DMODEL * DMODEL;
        const size_t wdf = (size_t)L * DMODEL * DFF;
        const size_t vd  = (size_t)L * DMODEL;
        const size_t vf  = (size_t)L * DFF;

        gemm_qkv<<<gQKV, 256>>>(x, Wq + wdd, Wk + wdd, Wv + wdd,
                                bq + vd, bk + vd, bv + vd, q, k, v);

        attn_mma<<<gAttn, 128, ATTN2_SMEM>>>(q, k, v, attn);

        gemm_mma<<<gProj, 256>>>(attn, Wo + wdd, bo + vd, x, tmp,
                                 MROWS, DMODEL, DMODEL, 0);
        ln_kernel<<<MROWS, 128>>>(tmp, g1 + vd, be1 + vd, x);

        gemm_mma<<<gFF1, 256>>>(x, W1 + wdf, b1 + vf, nullptr, ff,
                                MROWS, DFF, DMODEL, 1);
        gemm_mma<<<gProj, 256>>>(ff, W2 + wdf, b2 + vd, x, tmp,
                                 MROWS, DMODEL, DFF, 0);
        ln_kernel<<<MROWS, 128>>>(tmp, g2 + vd, be2 + vd,
                                  (L == NLAYERS - 1) ? outp : x);
    }
}

// round 6
// speedup vs baseline: 2.3156x; 1.0477x over previous
#include <cuda_runtime.h>
#include <cuda_bf16.h>
#include <cstdint>
#include <cstddef>

// Problem constants
#define BATCH   4
#define SEQ     2048
#define DMODEL  512
#define NHEADS  8
#define HDIM    64
#define DFF     2048
#define NLAYERS 6
#define MROWS   (BATCH * SEQ)            // 8192

// -------- scratch (device globals; no allocation allowed) --------
__device__ float g_x   [MROWS * DMODEL];
__device__ float g_q   [MROWS * DMODEL];
__device__ float g_k   [MROWS * DMODEL];
__device__ float g_v   [MROWS * DMODEL];
__device__ float g_attn[MROWS * DMODEL];
__device__ float g_tmp [MROWS * DMODEL];
__device__ float g_ff  [MROWS * DFF];
// tf32-rounded weights (segmented by tensor):
// Wq[6*262144] Wk[..] Wv[..] Wo[..] W1[6*1048576] W2[6*1048576]
#define WR_TOTAL 18874368
__device__ float g_wr  [WR_TOTAL];

// ==================== helpers ====================
__device__ __forceinline__ uint32_t f2tf32(float x) {
    uint32_t u;
    asm("cvt.rna.tf32.f32 %0, %1;" : "=r"(u) : "f"(x));
    return u;
}
__device__ __forceinline__ uint4 cvt4(float4 v) {
    return make_uint4(f2tf32(v.x), f2tf32(v.y), f2tf32(v.z), f2tf32(v.w));
}
__device__ __forceinline__ uint32_t smem_u32(const void* p) {
    uint32_t a;
    asm("{ .reg .u64 t; cvta.to.shared.u64 t, %1; cvt.u32.u64 %0, t; }"
        : "=r"(a) : "l"(p));
    return a;
}
__device__ __forceinline__ void cp16(uint32_t dst, const void* src) {
    asm volatile("cp.async.cg.shared.global [%0], [%1], 16;"
                 :: "r"(dst), "l"(src));
}
#define CP_COMMIT() asm volatile("cp.async.commit_group;" ::: "memory")
#define CP_WAIT0()  asm volatile("cp.async.wait_group 0;" ::: "memory")

// mma.sync m16n8k8 tf32: d = a*b + c  (f32 accum)
__device__ __forceinline__ void mma_tf32(
    float* d, const uint32_t* a, const uint32_t* b, const float* c)
{
    asm volatile(
        "mma.sync.aligned.m16n8k8.row.col.f32.tf32.tf32.f32 "
        "{%0,%1,%2,%3}, {%4,%5,%6,%7}, {%8,%9}, {%10,%11,%12,%13};"
        : "=f"(d[0]), "=f"(d[1]), "=f"(d[2]), "=f"(d[3])
        : "r"(a[0]), "r"(a[1]), "r"(a[2]), "r"(a[3]),
          "r"(b[0]), "r"(b[1]),
          "f"(c[0]), "f"(c[1]), "f"(c[2]), "f"(c[3]));
}

// =====================================================================
// Weight rounding pass: fp32 -> tf32(rna) bit pattern, float4 strided
// =====================================================================
__global__ void __launch_bounds__(256) round_kernel(
    const float* __restrict__ in, float* __restrict__ out, int n4)
{
    int i = blockIdx.x * blockDim.x + threadIdx.x;
    if (i < n4) {
        float4 v = *(const float4*)(in + i * 4);
        uint4 u = cvt4(v);
        *(uint4*)(out + i * 4) = u;
    }
}

// =====================================================================
// Embedding + positional encoding
// =====================================================================
__global__ void __launch_bounds__(128) embed_kernel(
    const int* __restrict__ src, const float* __restrict__ emb,
    const float* __restrict__ pe, float* __restrict__ x)
{
    int bl  = blockIdx.x;
    int l   = bl & (SEQ - 1);
    int tok = src[bl];
    int c   = threadIdx.x * 4;
    float4 e = *(const float4*)(emb + (size_t)tok * DMODEL + c);
    float4 p = *(const float4*)(pe  + (size_t)l   * DMODEL + c);
    float4 o; o.x = e.x + p.x; o.y = e.y + p.y; o.z = e.z + p.z; o.w = e.w + p.w;
    *(float4*)(x + (size_t)bl * DMODEL + c) = o;
}

// =====================================================================
// Tensor-core GEMM v2 (tf32 mma.sync): C = A@W + bias (+res)(+relu)
// CTA 128x128, 4 warps (2x2 of 64x64 warp tiles), K stages of 32,
// A: LDG+cvt.rna+STS ([m][36] natural layout, conflict-free),
// B: cp.async from pre-rounded weights ([k][136], conflict-free),
// double buffered.
// =====================================================================
#define KC2     32
#define ASTRIDE 36
#define BSTRIDE 136
#define A_WORDS (128 * ASTRIDE)          // per buffer
#define B_WORDS (KC2 * BSTRIDE)
#define GS_SMEM ((2 * A_WORDS + 2 * B_WORDS) * 4)   // 71680 bytes

__device__ __forceinline__ void gemm_body(
    const float* __restrict__ A, const float* __restrict__ Wr,
    const float* __restrict__ bias, const float* __restrict__ res,
    float* __restrict__ C, int M, int N, int K, int relu,
    int bxx, int byy)
{
    extern __shared__ uint32_t sm[];
    uint32_t* Asm[2] = { sm, sm + A_WORDS };
    uint32_t* Bsm[2] = { sm + 2 * A_WORDS, sm + 2 * A_WORDS + B_WORDS };
    uint32_t sbase = smem_u32(sm);
    uint32_t bB[2] = { sbase + 2 * A_WORDS * 4,
                       sbase + (2 * A_WORDS + B_WORDS) * 4 };

    int tid  = threadIdx.x;
    int lane = tid & 31;
    int wid  = tid >> 5;
    int bm = byy << 7, bn = bxx << 7;
    int warpM = (wid >> 1) * 64;
    int warpN = (wid & 1) * 64;
    int r0 = lane >> 2, c0 = lane & 3;

    // loaders
    const float* Ag = A + (size_t)(bm + tid) * K;        // one row per thread
    int bk = tid >> 2;                                    // 0..31 (k row)
    int bc = (tid & 3) * 4;                               // word col base
    const float* Bg = Wr + (size_t)bk * N + bn + bc;
    uint32_t bDstBase = (bk * BSTRIDE + bc) * 4;

    float acc[4][8][4];
#pragma unroll
    for (int mt = 0; mt < 4; mt++)
#pragma unroll
        for (int nt = 0; nt < 8; nt++)
#pragma unroll
            for (int r = 0; r < 4; r++) acc[mt][nt][r] = 0.f;

    int nst = K / KC2;

    // ---- prolog: stage 0 ----
    float4 stA[8];
#pragma unroll
    for (int i = 0; i < 8; i++) stA[i] = *(const float4*)(Ag + i * 4);
#pragma unroll
    for (int i = 0; i < 8; i++)
        *(uint4*)&Asm[0][tid * ASTRIDE + i * 4] = cvt4(stA[i]);
#pragma unroll
    for (int j = 0; j < 8; j++)
        cp16(bB[0] + bDstBase + j * 64, Bg + j * 16);
    CP_COMMIT();
    CP_WAIT0();
    __syncthreads();

    for (int s = 0; s < nst; s++) {
        int cur = s & 1, nb = cur ^ 1;
        bool more = (s + 1 < nst);
        if (more) {
            int kc = (s + 1) * KC2;
#pragma unroll
            for (int i = 0; i < 8; i++)
                stA[i] = *(const float4*)(Ag + kc + i * 4);
#pragma unroll
            for (int j = 0; j < 8; j++)
                cp16(bB[nb] + bDstBase + j * 64,
                     Bg + (size_t)kc * N + j * 16);
            CP_COMMIT();
        }

        // ---- compute: 4 k-steps of 8 ----
        const uint32_t* Ab = Asm[cur];
        const uint32_t* Bb = Bsm[cur];
#pragma unroll
        for (int ks = 0; ks < 4; ks++) {
            int k0 = ks * 8 + c0;
            uint32_t af[4][4];
#pragma unroll
            for (int mt = 0; mt < 4; mt++) {
                int m0 = warpM + mt * 16 + r0;
                af[mt][0] = Ab[m0 * ASTRIDE + k0];
                af[mt][1] = Ab[(m0 + 8) * ASTRIDE + k0];
                af[mt][2] = Ab[m0 * ASTRIDE + k0 + 4];
                af[mt][3] = Ab[(m0 + 8) * ASTRIDE + k0 + 4];
            }
#pragma unroll
            for (int nt = 0; nt < 8; nt++) {
                int n0 = warpN + nt * 8 + r0;
                uint32_t bf[2];
                bf[0] = Bb[k0 * BSTRIDE + n0];
                bf[1] = Bb[(k0 + 4) * BSTRIDE + n0];
#pragma unroll
                for (int mt = 0; mt < 4; mt++)
                    mma_tf32(acc[mt][nt], af[mt], bf, acc[mt][nt]);
            }
        }

        if (more) {
#pragma unroll
            for (int i = 0; i < 8; i++)
                *(uint4*)&Asm[nb][tid * ASTRIDE + i * 4] = cvt4(stA[i]);
            CP_WAIT0();
            __syncthreads();
        }
    }

    // ---- epilogue ----
#pragma unroll
    for (int mt = 0; mt < 4; mt++) {
        int row0 = bm + warpM + mt * 16 + r0;
#pragma unroll
        for (int h = 0; h < 2; h++) {
            int row = row0 + h * 8;
            float* crow = C + (size_t)row * N;
            const float* rrow = res ? (res + (size_t)row * N) : nullptr;
#pragma unroll
            for (int nt = 0; nt < 8; nt++) {
                int col = bn + warpN + nt * 8 + 2 * c0;
                float2 b2 = *(const float2*)(bias + col);
                float2 o;
                o.x = acc[mt][nt][h * 2 + 0] + b2.x;
                o.y = acc[mt][nt][h * 2 + 1] + b2.y;
                if (rrow) {
                    float2 r2 = *(const float2*)(rrow + col);
                    o.x += r2.x; o.y += r2.y;
                }
                if (relu) { o.x = fmaxf(o.x, 0.f); o.y = fmaxf(o.y, 0.f); }
                *(float2*)(crow + col) = o;
            }
        }
    }
}

__global__ void __launch_bounds__(128, 2) gemm_mma(
    const float* __restrict__ A, const float* __restrict__ Wr,
    const float* __restrict__ bias, const float* __restrict__ res,
    float* __restrict__ C, int M, int N, int K, int relu)
{
    gemm_body(A, Wr, bias, res, C, M, N, K, relu, blockIdx.x, blockIdx.y);
}

// fused QKV: blockIdx.z selects {Wq,bq,q} / {Wk,bk,k} / {Wv,bv,v}
__global__ void __launch_bounds__(128, 2) gemm_qkv(
    const float* __restrict__ x,
    const float* __restrict__ Wq, const float* __restrict__ Wk,
    const float* __restrict__ Wv,
    const float* __restrict__ bq, const float* __restrict__ bk,
    const float* __restrict__ bv,
    float* __restrict__ q, float* __restrict__ k, float* __restrict__ v)
{
    const float* W; const float* bias; float* C;
    if (blockIdx.z == 0)      { W = Wq; bias = bq; C = q; }
    else if (blockIdx.z == 1) { W = Wk; bias = bk; C = k; }
    else                      { W = Wv; bias = bv; C = v; }
    gemm_body(x, W, bias, nullptr, C, MROWS, DMODEL, DMODEL, 0,
              blockIdx.x, blockIdx.y);
}

// =====================================================================
// Tensor-core flash attention (tf32 mma.sync) — round-5 known-good.
// =====================================================================
#define ATS 68
#define ATTN2_SMEM (4 * 64 * ATS * 4)

__device__ __forceinline__ void load_tile_tf32(
    const float* __restrict__ g, uint32_t* __restrict__ s, int tid)
{
#pragma unroll
    for (int p = 0; p < 8; p++) {
        int idx = (tid + p * 128) * 4;
        int row = idx >> 6, col = idx & 63;
        float4 v = *(const float4*)(g + idx);
        uint32_t* d = s + row * ATS + col;
        d[0] = f2tf32(v.x); d[1] = f2tf32(v.y);
        d[2] = f2tf32(v.z); d[3] = f2tf32(v.w);
    }
}

__global__ void __launch_bounds__(128, 2) attn_mma(
    const float* __restrict__ q, const float* __restrict__ k,
    const float* __restrict__ v, float* __restrict__ out)
{
    extern __shared__ uint32_t smu[];
    uint32_t* Qs = smu;
    uint32_t* Ks = Qs + 64 * ATS;
    uint32_t* Vs = Ks + 64 * ATS;
    uint32_t* Ps = Vs + 64 * ATS;

    int tid  = threadIdx.x;
    int lane = tid & 31;
    int wid  = tid >> 5;
    int bh   = blockIdx.y;
    int qt   = blockIdx.x;
    int b    = bh >> 3, h = bh & 7;

    const float* Qg = q + ((size_t)bh * SEQ + qt * 64) * HDIM;
    const float* Kg = k + (size_t)bh * SEQ * HDIM;
    const float* Vg = v + (size_t)bh * SEQ * HDIM;

    load_tile_tf32(Qg, Qs, tid);

    int warpM = wid * 16;
    int r0 = lane >> 2, c0 = lane & 3;

    float m0 = -1e30f, m1 = -1e30f, l0 = 0.f, l1 = 0.f;
    float o_acc[8][4];
#pragma unroll
    for (int nt = 0; nt < 8; nt++)
#pragma unroll
        for (int r = 0; r < 4; r++) o_acc[nt][r] = 0.f;

    for (int kt = 0; kt < SEQ / 64; kt++) {
        __syncthreads();
        load_tile_tf32(Kg + (size_t)kt * 64 * HDIM, Ks, tid);
        load_tile_tf32(Vg + (size_t)kt * 64 * HDIM, Vs, tid);
        __syncthreads();

        float sacc[8][4];
#pragma unroll
        for (int nt = 0; nt < 8; nt++)
#pragma unroll
            for (int r = 0; r < 4; r++) sacc[nt][r] = 0.f;

#pragma unroll
        for (int ks = 0; ks < 8; ks++) {
            int kk = ks * 8 + c0;
            uint32_t a[4];
            a[0] = Qs[(warpM + r0) * ATS + kk];
            a[1] = Qs[(warpM + r0 + 8) * ATS + kk];
            a[2] = Qs[(warpM + r0) * ATS + kk + 4];
            a[3] = Qs[(warpM + r0 + 8) * ATS + kk + 4];
#pragma unroll
            for (int nt = 0; nt < 8; nt++) {
                uint32_t bb[2];
                bb[0] = Ks[(nt * 8 + r0) * ATS + kk];
                bb[1] = Ks[(nt * 8 + r0) * ATS + kk + 4];
                mma_tf32(sacc[nt], a, bb, sacc[nt]);
            }
        }

        float mt0 = -1e30f, mt1 = -1e30f;
#pragma unroll
        for (int nt = 0; nt < 8; nt++) {
#pragma unroll
            for (int r = 0; r < 4; r++) sacc[nt][r] *= 0.125f;
            mt0 = fmaxf(mt0, fmaxf(sacc[nt][0], sacc[nt][1]));
            mt1 = fmaxf(mt1, fmaxf(sacc[nt][2], sacc[nt][3]));
        }
        mt0 = fmaxf(mt0, __shfl_xor_sync(0xffffffffu, mt0, 1));
        mt0 = fmaxf(mt0, __shfl_xor_sync(0xffffffffu, mt0, 2));
        mt1 = fmaxf(mt1, __shfl_xor_sync(0xffffffffu, mt1, 1));
        mt1 = fmaxf(mt1, __shfl_xor_sync(0xffffffffu, mt1, 2));

        float mn0 = fmaxf(m0, mt0), mn1 = fmaxf(m1, mt1);
        float corr0 = __expf(m0 - mn0), corr1 = __expf(m1 - mn1);
        m0 = mn0; m1 = mn1;

        float rs0 = 0.f, rs1 = 0.f;
#pragma unroll
        for (int nt = 0; nt < 8; nt++) {
            float p00 = __expf(sacc[nt][0] - mn0);
            float p01 = __expf(sacc[nt][1] - mn0);
            float p10 = __expf(sacc[nt][2] - mn1);
            float p11 = __expf(sacc[nt][3] - mn1);
            rs0 += p00 + p01; rs1 += p10 + p11;
            uint2 u0 = make_uint2(f2tf32(p00), f2tf32(p01));
            uint2 u1 = make_uint2(f2tf32(p10), f2tf32(p11));
            *(uint2*)&Ps[(warpM + r0) * ATS + nt * 8 + 2 * c0] = u0;
            *(uint2*)&Ps[(warpM + r0 + 8) * ATS + nt * 8 + 2 * c0] = u1;
        }
        rs0 += __shfl_xor_sync(0xffffffffu, rs0, 1);
        rs0 += __shfl_xor_sync(0xffffffffu, rs0, 2);
        rs1 += __shfl_xor_sync(0xffffffffu, rs1, 1);
        rs1 += __shfl_xor_sync(0xffffffffu, rs1, 2);
        l0 = l0 * corr0 + rs0;
        l1 = l1 * corr1 + rs1;

#pragma unroll
        for (int nt = 0; nt < 8; nt++) {
            o_acc[nt][0] *= corr0; o_acc[nt][1] *= corr0;
            o_acc[nt][2] *= corr1; o_acc[nt][3] *= corr1;
        }
        __syncwarp();

#pragma unroll
        for (int ks = 0; ks < 8; ks++) {
            int kk = ks * 8;
            uint32_t a[4];
            a[0] = Ps[(warpM + r0) * ATS + kk + c0];
            a[1] = Ps[(warpM + r0 + 8) * ATS + kk + c0];
            a[2] = Ps[(warpM + r0) * ATS + kk + c0 + 4];
            a[3] = Ps[(warpM + r0 + 8) * ATS + kk + c0 + 4];
#pragma unroll
            for (int nt = 0; nt < 8; nt++) {
                uint32_t bb[2];
                bb[0] = Vs[(kk + c0) * ATS + nt * 8 + r0];
                bb[1] = Vs[(kk + c0 + 4) * ATS + nt * 8 + r0];
                mma_tf32(o_acc[nt], a, bb, o_acc[nt]);
            }
        }
    }

    float inv0 = 1.0f / l0, inv1 = 1.0f / l1;
    size_t row0 = (size_t)b * SEQ + qt * 64 + warpM + r0;
    float* O0 = out + row0 * DMODEL + h * HDIM;
    float* O1 = O0 + 8 * DMODEL;
#pragma unroll
    for (int nt = 0; nt < 8; nt++) {
        int col = nt * 8 + 2 * c0;
        float2 a = make_float2(o_acc[nt][0] * inv0, o_acc[nt][1] * inv0);
        float2 c = make_float2(o_acc[nt][2] * inv1, o_acc[nt][3] * inv1);
        *(float2*)(O0 + col) = a;
        *(float2*)(O1 + col) = c;
    }
}

// =====================================================================
// LayerNorm over last dim (512). Block per row, 128 threads.
// =====================================================================
__global__ void __launch_bounds__(128) ln_kernel(
    const float* __restrict__ in, const float* __restrict__ g,
    const float* __restrict__ b, float* __restrict__ out)
{
    int row = blockIdx.x;
    int tid = threadIdx.x;
    float4 v4 = *(const float4*)(in + (size_t)row * DMODEL + tid * 4);
    float s  = v4.x + v4.y + v4.z + v4.w;
    float sq = v4.x * v4.x + v4.y * v4.y + v4.z * v4.z + v4.w * v4.w;
#pragma unroll
    for (int off = 16; off > 0; off >>= 1) {
        s  += __shfl_xor_sync(0xffffffffu, s, off);
        sq += __shfl_xor_sync(0xffffffffu, sq, off);
    }
    __shared__ float ss[4], sqs[4];
    int wid = tid >> 5;
    if ((tid & 31) == 0) { ss[wid] = s; sqs[wid] = sq; }
    __syncthreads();
    s  = ss[0] + ss[1] + ss[2] + ss[3];
    sq = sqs[0] + sqs[1] + sqs[2] + sqs[3];
    float mu  = s * (1.0f / DMODEL);
    float var = sq * (1.0f / DMODEL) - mu * mu;
    float inv = rsqrtf(var + 1e-5f);
    float4 gv = *(const float4*)(g + tid * 4);
    float4 bv = *(const float4*)(b + tid * 4);
    float4 o;
    o.x = (v4.x - mu) * inv * gv.x + bv.x;
    o.y = (v4.y - mu) * inv * gv.y + bv.y;
    o.z = (v4.z - mu) * inv * gv.z + bv.z;
    o.w = (v4.w - mu) * inv * gv.w + bv.w;
    *(float4*)(out + (size_t)row * DMODEL + tid * 4) = o;
}

// =====================================================================
// host launcher
// =====================================================================
extern "C" void kernel_launch(void* const* d_in, const int* in_sizes, int n_in,
                              void* d_out, int out_size)
{
    const int*   src  = (const int*)  d_in[0];
    const float* emb  = (const float*)d_in[1];
    const float* pe   = (const float*)d_in[2];
    const float* Wq   = (const float*)d_in[3];
    const float* bq   = (const float*)d_in[4];
    const float* Wk   = (const float*)d_in[5];
    const float* bk   = (const float*)d_in[6];
    const float* Wv   = (const float*)d_in[7];
    const float* bv   = (const float*)d_in[8];
    const float* Wo   = (const float*)d_in[9];
    const float* bo   = (const float*)d_in[10];
    const float* W1   = (const float*)d_in[11];
    const float* b1   = (const float*)d_in[12];
    const float* W2   = (const float*)d_in[13];
    const float* b2   = (const float*)d_in[14];
    const float* g1   = (const float*)d_in[15];
    const float* be1  = (const float*)d_in[16];
    const float* g2   = (const float*)d_in[17];
    const float* be2  = (const float*)d_in[18];
    float* outp = (float*)d_out;

    float *x, *q, *k, *v, *attn, *tmp, *ff, *wr;
    cudaGetSymbolAddress((void**)&x,    g_x);
    cudaGetSymbolAddress((void**)&q,    g_q);
    cudaGetSymbolAddress((void**)&k,    g_k);
    cudaGetSymbolAddress((void**)&v,    g_v);
    cudaGetSymbolAddress((void**)&attn, g_attn);
    cudaGetSymbolAddress((void**)&tmp,  g_tmp);
    cudaGetSymbolAddress((void**)&ff,   g_ff);
    cudaGetSymbolAddress((void**)&wr,   g_wr);

    cudaFuncSetAttribute(attn_mma,
                         cudaFuncAttributeMaxDynamicSharedMemorySize, ATTN2_SMEM);
    cudaFuncSetAttribute(gemm_mma,
                         cudaFuncAttributeMaxDynamicSharedMemorySize, GS_SMEM);
    cudaFuncSetAttribute(gemm_qkv,
                         cudaFuncAttributeMaxDynamicSharedMemorySize, GS_SMEM);

    // rounded-weight segments
    const size_t DD6 = (size_t)NLAYERS * DMODEL * DMODEL;   // 1572864
    const size_t DF6 = (size_t)NLAYERS * DMODEL * DFF;      // 6291456
    float* WqR = wr;
    float* WkR = WqR + DD6;
    float* WvR = WkR + DD6;
    float* WoR = WvR + DD6;
    float* W1R = WoR + DD6;
    float* W2R = W1R + DF6;

    round_kernel<<<(int)(DD6 / 4 / 256), 256>>>(Wq, WqR, (int)(DD6 / 4));
    round_kernel<<<(int)(DD6 / 4 / 256), 256>>>(Wk, WkR, (int)(DD6 / 4));
    round_kernel<<<(int)(DD6 / 4 / 256), 256>>>(Wv, WvR, (int)(DD6 / 4));
    round_kernel<<<(int)(DD6 / 4 / 256), 256>>>(Wo, WoR, (int)(DD6 / 4));
    round_kernel<<<(int)(DF6 / 4 / 256), 256>>>(W1, W1R, (int)(DF6 / 4));
    round_kernel<<<(int)(DF6 / 4 / 256), 256>>>(W2, W2R, (int)(DF6 / 4));

    embed_kernel<<<MROWS, 128>>>(src, emb, pe, x);

    dim3 gQKV(DMODEL / 128, MROWS / 128, 3);  // (4, 64, 3)
    dim3 gProj(DMODEL / 128, MROWS / 128);    // (4, 64)
    dim3 gFF1(DFF / 128,    MROWS / 128);     // (16, 64)
    dim3 gAttn(SEQ / 64, BATCH * NHEADS);     // (32, 32)

    for (int L = 0; L < NLAYERS; L++) {
        const size_t wdd = (size_t)L * DMODEL * DMODEL;
        const size_t wdf = (size_t)L * DMODEL * DFF;
        const size_t vd  = (size_t)L * DMODEL;
        const size_t vf  = (size_t)L * DFF;

        gemm_qkv<<<gQKV, 128, GS_SMEM>>>(x, WqR + wdd, WkR + wdd, WvR + wdd,
                                         bq + vd, bk + vd, bv + vd, q, k, v);

        attn_mma<<<gAttn, 128, ATTN2_SMEM>>>(q, k, v, attn);

        gemm_mma<<<gProj, 128, GS_SMEM>>>(attn, WoR + wdd, bo + vd, x, tmp,
                                          MROWS, DMODEL, DMODEL, 0);
        ln_kernel<<<MROWS, 128>>>(tmp, g1 + vd, be1 + vd, x);

        gemm_mma<<<gFF1, 128, GS_SMEM>>>(x, W1R + wdf, b1 + vf, nullptr, ff,
                                         MROWS, DFF, DMODEL, 1);
        gemm_mma<<<gProj, 128, GS_SMEM>>>(ff, W2R + wdf, b2 + vd, x, tmp,
                                          MROWS, DMODEL, DFF, 0);
        ln_kernel<<<MROWS, 128>>>(tmp, g2 + vd, be2 + vd,
                                  (L == NLAYERS - 1) ? outp : x);
    }
}

// round 7
// speedup vs baseline: 2.9840x; 1.2886x over previous
#include <cuda_runtime.h>
#include <cuda_bf16.h>
#include <cstdint>
#include <cstddef>

// Problem constants
#define BATCH   4
#define SEQ     2048
#define DMODEL  512
#define NHEADS  8
#define HDIM    64
#define DFF     2048
#define NLAYERS 6
#define MROWS   (BATCH * SEQ)            // 8192

// -------- scratch (device globals; no allocation allowed) --------
__device__ float g_x   [MROWS * DMODEL];
__device__ float g_q   [MROWS * DMODEL];
__device__ float g_k   [MROWS * DMODEL];
__device__ float g_v   [MROWS * DMODEL];
__device__ float g_attn[MROWS * DMODEL];
__device__ float g_tmp [MROWS * DMODEL];
__device__ float g_ff  [MROWS * DFF];
// tf32-rounded weights
#define WR_TOTAL 18874368
__device__ float g_wr  [WR_TOTAL];

// ==================== helpers ====================
__device__ __forceinline__ uint32_t f2tf32(float x) {
    uint32_t u;
    asm("cvt.rna.tf32.f32 %0, %1;" : "=r"(u) : "f"(x));
    return u;
}
__device__ __forceinline__ float rnd_tf32(float x) {
    return __uint_as_float(f2tf32(x));
}
__device__ __forceinline__ uint4 cvt4(float4 v) {
    return make_uint4(f2tf32(v.x), f2tf32(v.y), f2tf32(v.z), f2tf32(v.w));
}
__device__ __forceinline__ uint32_t smem_u32(const void* p) {
    uint32_t a;
    asm("{ .reg .u64 t; cvta.to.shared.u64 t, %1; cvt.u32.u64 %0, t; }"
        : "=r"(a) : "l"(p));
    return a;
}
__device__ __forceinline__ void cp16(uint32_t dst, const void* src) {
    asm volatile("cp.async.cg.shared.global [%0], [%1], 16;"
                 :: "r"(dst), "l"(src));
}
#define CP_COMMIT() asm volatile("cp.async.commit_group;" ::: "memory")
#define CP_WAIT0()  asm volatile("cp.async.wait_group 0;" ::: "memory")
#define CP_WAIT1()  asm volatile("cp.async.wait_group 1;" ::: "memory")

// mma.sync m16n8k8 tf32: d = a*b + c  (f32 accum)
__device__ __forceinline__ void mma_tf32(
    float* d, const uint32_t* a, const uint32_t* b, const float* c)
{
    asm volatile(
        "mma.sync.aligned.m16n8k8.row.col.f32.tf32.tf32.f32 "
        "{%0,%1,%2,%3}, {%4,%5,%6,%7}, {%8,%9}, {%10,%11,%12,%13};"
        : "=f"(d[0]), "=f"(d[1]), "=f"(d[2]), "=f"(d[3])
        : "r"(a[0]), "r"(a[1]), "r"(a[2]), "r"(a[3]),
          "r"(b[0]), "r"(b[1]),
          "f"(c[0]), "f"(c[1]), "f"(c[2]), "f"(c[3]));
}

// =====================================================================
// Weight rounding pass
// =====================================================================
__global__ void __launch_bounds__(256) round_kernel(
    const float* __restrict__ in, float* __restrict__ out, int n4)
{
    int i = blockIdx.x * blockDim.x + threadIdx.x;
    if (i < n4) {
        float4 v = *(const float4*)(in + i * 4);
        uint4 u = cvt4(v);
        *(uint4*)(out + i * 4) = u;
    }
}

// =====================================================================
// Embedding + positional encoding (output tf32-rounded)
// =====================================================================
__global__ void __launch_bounds__(128) embed_kernel(
    const int* __restrict__ src, const float* __restrict__ emb,
    const float* __restrict__ pe, float* __restrict__ x)
{
    int bl  = blockIdx.x;
    int l   = bl & (SEQ - 1);
    int tok = src[bl];
    int c   = threadIdx.x * 4;
    float4 e = *(const float4*)(emb + (size_t)tok * DMODEL + c);
    float4 p = *(const float4*)(pe  + (size_t)l   * DMODEL + c);
    uint4 o = make_uint4(f2tf32(e.x + p.x), f2tf32(e.y + p.y),
                         f2tf32(e.z + p.z), f2tf32(e.w + p.w));
    *(uint4*)(x + (size_t)bl * DMODEL + c) = o;
}

// =====================================================================
// Tensor-core GEMM v3 (tf32 mma.sync): C = A@W + bias (+res)(+relu)(+rnd)
// Both operands pre-rounded tf32 in gmem -> pure cp.async pipeline.
// CTA 128x128, 8 warps (2x4, warp tile 64x32), KC=32, 3-stage pipeline.
// A smem [128][36] (conflict-free), B smem [32][136] (conflict-free).
// =====================================================================
#define KC3    32
#define AW     36
#define BW     136
#define A_STG  (128 * AW)                 // 4608 words
#define B_STG  (KC3 * BW)                 // 4352 words
#define STG_W  (A_STG + B_STG)            // 8960 words
#define GS3_SMEM (3 * STG_W * 4)          // 107520 bytes

__device__ __forceinline__ void gemm_body(
    const float* __restrict__ A, const float* __restrict__ Wr,
    const float* __restrict__ bias, const float* __restrict__ res,
    float* __restrict__ C, int M, int N, int K, int relu, int rnd,
    int bxx, int byy)
{
    extern __shared__ uint32_t sm[];
    uint32_t sbase = smem_u32(sm);

    int tid  = threadIdx.x;
    int lane = tid & 31;
    int wid  = tid >> 5;
    int bm = byy << 7, bn = bxx << 7;
    int warpM = (wid >> 2) * 64;
    int warpN = (wid & 3) * 32;
    int r0 = lane >> 2, c0 = lane & 3;

    // loader mappings (256 threads, 4 x 16B chunks each per operand)
    int aRow[4], aC16[4], bKr[4], bC16[4];
#pragma unroll
    for (int i = 0; i < 4; i++) {
        int id = tid + i * 256;
        aRow[i] = id >> 3;  aC16[i] = id & 7;     // A: 128 rows x 8 chunks
        bKr[i]  = id >> 5;  bC16[i] = id & 31;    // B: 32 rows x 32 chunks
    }

    float acc[4][4][4];
#pragma unroll
    for (int mt = 0; mt < 4; mt++)
#pragma unroll
        for (int nt = 0; nt < 4; nt++)
#pragma unroll
            for (int r = 0; r < 4; r++) acc[mt][nt][r] = 0.f;

    int nst = K / KC3;

    // issue one stage's loads into stage slot st at k offset kc
    auto issue_stage = [&](int st, int kc) {
        uint32_t aB = sbase + (st * STG_W) * 4;
        uint32_t bBq = sbase + (st * STG_W + A_STG) * 4;
#pragma unroll
        for (int i = 0; i < 4; i++)
            cp16(aB + (aRow[i] * AW + aC16[i] * 4) * 4,
                 A + (size_t)(bm + aRow[i]) * K + kc + aC16[i] * 4);
#pragma unroll
        for (int i = 0; i < 4; i++)
            cp16(bBq + (bKr[i] * BW + bC16[i] * 4) * 4,
                 Wr + (size_t)(kc + bKr[i]) * N + bn + bC16[i] * 4);
        CP_COMMIT();
    };

    issue_stage(0, 0);
    issue_stage(1, KC3);

    for (int s = 0; s < nst; s++) {
        int cur = s % 3;
        if (s + 1 < nst) CP_WAIT1(); else CP_WAIT0();
        __syncthreads();
        if (s + 2 < nst) issue_stage((s + 2) % 3, (s + 2) * KC3);

        const uint32_t* Ab = sm + cur * STG_W;
        const uint32_t* Bb = Ab + A_STG;
#pragma unroll
        for (int ks = 0; ks < 4; ks++) {
            int k0 = ks * 8 + c0;
            uint32_t af[4][4], bf[4][2];
#pragma unroll
            for (int mt = 0; mt < 4; mt++) {
                int m0 = warpM + mt * 16 + r0;
                af[mt][0] = Ab[m0 * AW + k0];
                af[mt][1] = Ab[(m0 + 8) * AW + k0];
                af[mt][2] = Ab[m0 * AW + k0 + 4];
                af[mt][3] = Ab[(m0 + 8) * AW + k0 + 4];
            }
#pragma unroll
            for (int nt = 0; nt < 4; nt++) {
                int n0 = warpN + nt * 8 + r0;
                bf[nt][0] = Bb[k0 * BW + n0];
                bf[nt][1] = Bb[(k0 + 4) * BW + n0];
            }
#pragma unroll
            for (int mt = 0; mt < 4; mt++)
#pragma unroll
                for (int nt = 0; nt < 4; nt++)
                    mma_tf32(acc[mt][nt], af[mt], bf[nt], acc[mt][nt]);
        }
        __syncthreads();
    }

    // ---- epilogue ----
#pragma unroll
    for (int mt = 0; mt < 4; mt++) {
        int row0 = bm + warpM + mt * 16 + r0;
#pragma unroll
        for (int h = 0; h < 2; h++) {
            int row = row0 + h * 8;
            float* crow = C + (size_t)row * N;
            const float* rrow = res ? (res + (size_t)row * N) : nullptr;
#pragma unroll
            for (int nt = 0; nt < 4; nt++) {
                int col = bn + warpN + nt * 8 + 2 * c0;
                float2 b2 = *(const float2*)(bias + col);
                float2 o;
                o.x = acc[mt][nt][h * 2 + 0] + b2.x;
                o.y = acc[mt][nt][h * 2 + 1] + b2.y;
                if (rrow) {
                    float2 r2 = *(const float2*)(rrow + col);
                    o.x += r2.x; o.y += r2.y;
                }
                if (relu) { o.x = fmaxf(o.x, 0.f); o.y = fmaxf(o.y, 0.f); }
                if (rnd)  { o.x = rnd_tf32(o.x);   o.y = rnd_tf32(o.y); }
                *(float2*)(crow + col) = o;
            }
        }
    }
}

__global__ void __launch_bounds__(256, 2) gemm_mma(
    const float* __restrict__ A, const float* __restrict__ Wr,
    const float* __restrict__ bias, const float* __restrict__ res,
    float* __restrict__ C, int M, int N, int K, int relu, int rnd)
{
    gemm_body(A, Wr, bias, res, C, M, N, K, relu, rnd,
              blockIdx.x, blockIdx.y);
}

// fused QKV: blockIdx.z selects weight/bias/output set
__global__ void __launch_bounds__(256, 2) gemm_qkv(
    const float* __restrict__ x,
    const float* __restrict__ Wq, const float* __restrict__ Wk,
    const float* __restrict__ Wv,
    const float* __restrict__ bq, const float* __restrict__ bk,
    const float* __restrict__ bv,
    float* __restrict__ q, float* __restrict__ k, float* __restrict__ v)
{
    const float* W; const float* bias; float* C;
    if (blockIdx.z == 0)      { W = Wq; bias = bq; C = q; }
    else if (blockIdx.z == 1) { W = Wk; bias = bk; C = k; }
    else                      { W = Wv; bias = bv; C = v; }
    gemm_body(x, W, bias, nullptr, C, MROWS, DMODEL, DMODEL, 0, 1,
              blockIdx.x, blockIdx.y);
}

// =====================================================================
// Tensor-core flash attention (tf32 mma.sync), cp.async loads,
// double-buffered K/V. q/k/v arrive pre-rounded tf32.
// smem: Q | P | K0 | V0 | K1 | V1, each 64x68 words.
// =====================================================================
#define ATS 68
#define TILE_W (64 * ATS)                 // 4352 words
#define ATTN3_SMEM (6 * TILE_W * 4)       // 104448 bytes

__device__ __forceinline__ void cp_tile(
    uint32_t dstbase, const float* __restrict__ g, int tid)
{
#pragma unroll
    for (int i = 0; i < 8; i++) {
        int id  = tid + i * 128;
        int row = id >> 4, c16 = id & 15;
        cp16(dstbase + (row * ATS + c16 * 4) * 4, g + row * 64 + c16 * 4);
    }
}

__global__ void __launch_bounds__(128, 2) attn_mma(
    const float* __restrict__ q, const float* __restrict__ k,
    const float* __restrict__ v, float* __restrict__ out)
{
    extern __shared__ uint32_t smu[];
    uint32_t sbase = smem_u32(smu);
    uint32_t* Qs = smu;
    uint32_t* Ps = smu + TILE_W;

    int tid  = threadIdx.x;
    int lane = tid & 31;
    int wid  = tid >> 5;
    int bh   = blockIdx.y;
    int qt   = blockIdx.x;
    int b    = bh >> 3, h = bh & 7;

    const float* Qg = q + ((size_t)bh * SEQ + qt * 64) * HDIM;
    const float* Kg = k + (size_t)bh * SEQ * HDIM;
    const float* Vg = v + (size_t)bh * SEQ * HDIM;

    // prolog: Q + K0 + V0 in one group
    cp_tile(sbase, Qg, tid);
    cp_tile(sbase + (2 * TILE_W) * 4, Kg, tid);
    cp_tile(sbase + (3 * TILE_W) * 4, Vg, tid);
    CP_COMMIT();

    int warpM = wid * 16;
    int r0 = lane >> 2, c0 = lane & 3;

    float m0 = -1e30f, m1 = -1e30f, l0 = 0.f, l1 = 0.f;
    float o_acc[8][4];
#pragma unroll
    for (int nt = 0; nt < 8; nt++)
#pragma unroll
        for (int r = 0; r < 4; r++) o_acc[nt][r] = 0.f;

    for (int kt = 0; kt < SEQ / 64; kt++) {
        int cur = kt & 1, nb = cur ^ 1;
        CP_WAIT0();
        __syncthreads();
        if (kt + 1 < SEQ / 64) {
            cp_tile(sbase + ((2 + 2 * nb) * TILE_W) * 4,
                    Kg + (size_t)(kt + 1) * 64 * HDIM, tid);
            cp_tile(sbase + ((3 + 2 * nb) * TILE_W) * 4,
                    Vg + (size_t)(kt + 1) * 64 * HDIM, tid);
            CP_COMMIT();
        }
        const uint32_t* Ks = smu + (2 + 2 * cur) * TILE_W;
        const uint32_t* Vs = smu + (3 + 2 * cur) * TILE_W;

        // ---- S = Q K^T ----
        float sacc[8][4];
#pragma unroll
        for (int nt = 0; nt < 8; nt++)
#pragma unroll
            for (int r = 0; r < 4; r++) sacc[nt][r] = 0.f;

#pragma unroll
        for (int ks = 0; ks < 8; ks++) {
            int kk = ks * 8 + c0;
            uint32_t a[4];
            a[0] = Qs[(warpM + r0) * ATS + kk];
            a[1] = Qs[(warpM + r0 + 8) * ATS + kk];
            a[2] = Qs[(warpM + r0) * ATS + kk + 4];
            a[3] = Qs[(warpM + r0 + 8) * ATS + kk + 4];
#pragma unroll
            for (int nt = 0; nt < 8; nt++) {
                uint32_t bb[2];
                bb[0] = Ks[(nt * 8 + r0) * ATS + kk];
                bb[1] = Ks[(nt * 8 + r0) * ATS + kk + 4];
                mma_tf32(sacc[nt], a, bb, sacc[nt]);
            }
        }

        // ---- online softmax ----
        float mt0 = -1e30f, mt1 = -1e30f;
#pragma unroll
        for (int nt = 0; nt < 8; nt++) {
#pragma unroll
            for (int r = 0; r < 4; r++) sacc[nt][r] *= 0.125f;
            mt0 = fmaxf(mt0, fmaxf(sacc[nt][0], sacc[nt][1]));
            mt1 = fmaxf(mt1, fmaxf(sacc[nt][2], sacc[nt][3]));
        }
        mt0 = fmaxf(mt0, __shfl_xor_sync(0xffffffffu, mt0, 1));
        mt0 = fmaxf(mt0, __shfl_xor_sync(0xffffffffu, mt0, 2));
        mt1 = fmaxf(mt1, __shfl_xor_sync(0xffffffffu, mt1, 1));
        mt1 = fmaxf(mt1, __shfl_xor_sync(0xffffffffu, mt1, 2));

        float mn0 = fmaxf(m0, mt0), mn1 = fmaxf(m1, mt1);
        float corr0 = __expf(m0 - mn0), corr1 = __expf(m1 - mn1);
        m0 = mn0; m1 = mn1;

        float rs0 = 0.f, rs1 = 0.f;
#pragma unroll
        for (int nt = 0; nt < 8; nt++) {
            float p00 = __expf(sacc[nt][0] - mn0);
            float p01 = __expf(sacc[nt][1] - mn0);
            float p10 = __expf(sacc[nt][2] - mn1);
            float p11 = __expf(sacc[nt][3] - mn1);
            rs0 += p00 + p01; rs1 += p10 + p11;
            uint2 u0 = make_uint2(f2tf32(p00), f2tf32(p01));
            uint2 u1 = make_uint2(f2tf32(p10), f2tf32(p11));
            *(uint2*)&Ps[(warpM + r0) * ATS + nt * 8 + 2 * c0] = u0;
            *(uint2*)&Ps[(warpM + r0 + 8) * ATS + nt * 8 + 2 * c0] = u1;
        }
        rs0 += __shfl_xor_sync(0xffffffffu, rs0, 1);
        rs0 += __shfl_xor_sync(0xffffffffu, rs0, 2);
        rs1 += __shfl_xor_sync(0xffffffffu, rs1, 1);
        rs1 += __shfl_xor_sync(0xffffffffu, rs1, 2);
        l0 = l0 * corr0 + rs0;
        l1 = l1 * corr1 + rs1;

#pragma unroll
        for (int nt = 0; nt < 8; nt++) {
            o_acc[nt][0] *= corr0; o_acc[nt][1] *= corr0;
            o_acc[nt][2] *= corr1; o_acc[nt][3] *= corr1;
        }
        __syncwarp();

        // ---- O += P @ V ----
#pragma unroll
        for (int ks = 0; ks < 8; ks++) {
            int kk = ks * 8;
            uint32_t a[4];
            a[0] = Ps[(warpM + r0) * ATS + kk + c0];
            a[1] = Ps[(warpM + r0 + 8) * ATS + kk + c0];
            a[2] = Ps[(warpM + r0) * ATS + kk + c0 + 4];
            a[3] = Ps[(warpM + r0 + 8) * ATS + kk + c0 + 4];
#pragma unroll
            for (int nt = 0; nt < 8; nt++) {
                uint32_t bb[2];
                bb[0] = Vs[(kk + c0) * ATS + nt * 8 + r0];
                bb[1] = Vs[(kk + c0 + 4) * ATS + nt * 8 + r0];
                mma_tf32(o_acc[nt], a, bb, o_acc[nt]);
            }
        }
    }

    // epilogue: /l, round, scatter to [B, L, H*64 + d]
    float inv0 = 1.0f / l0, inv1 = 1.0f / l1;
    size_t row0 = (size_t)b * SEQ + qt * 64 + warpM + r0;
    float* O0 = out + row0 * DMODEL + h * HDIM;
    float* O1 = O0 + 8 * DMODEL;
#pragma unroll
    for (int nt = 0; nt < 8; nt++) {
        int col = nt * 8 + 2 * c0;
        float2 a = make_float2(rnd_tf32(o_acc[nt][0] * inv0),
                               rnd_tf32(o_acc[nt][1] * inv0));
        float2 c = make_float2(rnd_tf32(o_acc[nt][2] * inv1),
                               rnd_tf32(o_acc[nt][3] * inv1));
        *(float2*)(O0 + col) = a;
        *(float2*)(O1 + col) = c;
    }
}

// =====================================================================
// LayerNorm over last dim (512). Block per row, 128 threads.
// rnd=1: round output to tf32 (feeds next gemm); rnd=0 for final out.
// =====================================================================
__global__ void __launch_bounds__(128) ln_kernel(
    const float* __restrict__ in, const float* __restrict__ g,
    const float* __restrict__ b, float* __restrict__ out, int rnd)
{
    int row = blockIdx.x;
    int tid = threadIdx.x;
    float4 v4 = *(const float4*)(in + (size_t)row * DMODEL + tid * 4);
    float s  = v4.x + v4.y + v4.z + v4.w;
    float sq = v4.x * v4.x + v4.y * v4.y + v4.z * v4.z + v4.w * v4.w;
#pragma unroll
    for (int off = 16; off > 0; off >>= 1) {
        s  += __shfl_xor_sync(0xffffffffu, s, off);
        sq += __shfl_xor_sync(0xffffffffu, sq, off);
    }
    __shared__ float ss[4], sqs[4];
    int wid = tid >> 5;
    if ((tid & 31) == 0) { ss[wid] = s; sqs[wid] = sq; }
    __syncthreads();
    s  = ss[0] + ss[1] + ss[2] + ss[3];
    sq = sqs[0] + sqs[1] + sqs[2] + sqs[3];
    float mu  = s * (1.0f / DMODEL);
    float var = sq * (1.0f / DMODEL) - mu * mu;
    float inv = rsqrtf(var + 1e-5f);
    float4 gv = *(const float4*)(g + tid * 4);
    float4 bv = *(const float4*)(b + tid * 4);
    float4 o;
    o.x = (v4.x - mu) * inv * gv.x + bv.x;
    o.y = (v4.y - mu) * inv * gv.y + bv.y;
    o.z = (v4.z - mu) * inv * gv.z + bv.z;
    o.w = (v4.w - mu) * inv * gv.w + bv.w;
    if (rnd) {
        o.x = rnd_tf32(o.x); o.y = rnd_tf32(o.y);
        o.z = rnd_tf32(o.z); o.w = rnd_tf32(o.w);
    }
    *(float4*)(out + (size_t)row * DMODEL + tid * 4) = o;
}

// =====================================================================
// host launcher
// =====================================================================
extern "C" void kernel_launch(void* const* d_in, const int* in_sizes, int n_in,
                              void* d_out, int out_size)
{
    const int*   src  = (const int*)  d_in[0];
    const float* emb  = (const float*)d_in[1];
    const float* pe   = (const float*)d_in[2];
    const float* Wq   = (const float*)d_in[3];
    const float* bq   = (const float*)d_in[4];
    const float* Wk   = (const float*)d_in[5];
    const float* bk   = (const float*)d_in[6];
    const float* Wv   = (const float*)d_in[7];
    const float* bv   = (const float*)d_in[8];
    const float* Wo   = (const float*)d_in[9];
    const float* bo   = (const float*)d_in[10];
    const float* W1   = (const float*)d_in[11];
    const float* b1   = (const float*)d_in[12];
    const float* W2   = (const float*)d_in[13];
    const float* b2   = (const float*)d_in[14];
    const float* g1   = (const float*)d_in[15];
    const float* be1  = (const float*)d_in[16];
    const float* g2   = (const float*)d_in[17];
    const float* be2  = (const float*)d_in[18];
    float* outp = (float*)d_out;

    float *x, *q, *k, *v, *attn, *tmp, *ff, *wr;
    cudaGetSymbolAddress((void**)&x,    g_x);
    cudaGetSymbolAddress((void**)&q,    g_q);
    cudaGetSymbolAddress((void**)&k,    g_k);
    cudaGetSymbolAddress((void**)&v,    g_v);
    cudaGetSymbolAddress((void**)&attn, g_attn);
    cudaGetSymbolAddress((void**)&tmp,  g_tmp);
    cudaGetSymbolAddress((void**)&ff,   g_ff);
    cudaGetSymbolAddress((void**)&wr,   g_wr);

    cudaFuncSetAttribute(attn_mma,
                         cudaFuncAttributeMaxDynamicSharedMemorySize, ATTN3_SMEM);
    cudaFuncSetAttribute(gemm_mma,
                         cudaFuncAttributeMaxDynamicSharedMemorySize, GS3_SMEM);
    cudaFuncSetAttribute(gemm_qkv,
                         cudaFuncAttributeMaxDynamicSharedMemorySize, GS3_SMEM);

    const size_t DD6 = (size_t)NLAYERS * DMODEL * DMODEL;
    const size_t DF6 = (size_t)NLAYERS * DMODEL * DFF;
    float* WqR = wr;
    float* WkR = WqR + DD6;
    float* WvR = WkR + DD6;
    float* WoR = WvR + DD6;
    float* W1R = WoR + DD6;
    float* W2R = W1R + DF6;

    round_kernel<<<(int)(DD6 / 4 / 256), 256>>>(Wq, WqR, (int)(DD6 / 4));
    round_kernel<<<(int)(DD6 / 4 / 256), 256>>>(Wk, WkR, (int)(DD6 / 4));
    round_kernel<<<(int)(DD6 / 4 / 256), 256>>>(Wv, WvR, (int)(DD6 / 4));
    round_kernel<<<(int)(DD6 / 4 / 256), 256>>>(Wo, WoR, (int)(DD6 / 4));
    round_kernel<<<(int)(DF6 / 4 / 256), 256>>>(W1, W1R, (int)(DF6 / 4));
    round_kernel<<<(int)(DF6 / 4 / 256), 256>>>(W2, W2R, (int)(DF6 / 4));

    embed_kernel<<<MROWS, 128>>>(src, emb, pe, x);

    dim3 gQKV(DMODEL / 128, MROWS / 128, 3);  // (4, 64, 3)
    dim3 gProj(DMODEL / 128, MROWS / 128);    // (4, 64)
    dim3 gFF1(DFF / 128,    MROWS / 128);     // (16, 64)
    dim3 gAttn(SEQ / 64, BATCH * NHEADS);     // (32, 32)

    for (int L = 0; L < NLAYERS; L++) {
        const size_t wdd = (size_t)L * DMODEL * DMODEL;
        const size_t wdf = (size_t)L * DMODEL * DFF;
        const size_t vd  = (size_t)L * DMODEL;
        const size_t vf  = (size_t)L * DFF;

        gemm_qkv<<<gQKV, 256, GS3_SMEM>>>(x, WqR + wdd, WkR + wdd, WvR + wdd,
                                          bq + vd, bk + vd, bv + vd, q, k, v);

        attn_mma<<<gAttn, 128, ATTN3_SMEM>>>(q, k, v, attn);

        gemm_mma<<<gProj, 256, GS3_SMEM>>>(attn, WoR + wdd, bo + vd, x, tmp,
                                           MROWS, DMODEL, DMODEL, 0, 0);
        ln_kernel<<<MROWS, 128>>>(tmp, g1 + vd, be1 + vd, x, 1);

        gemm_mma<<<gFF1, 256, GS3_SMEM>>>(x, W1R + wdf, b1 + vf, nullptr, ff,
                                          MROWS, DFF, DMODEL, 1, 1);
        gemm_mma<<<gProj, 256, GS3_SMEM>>>(ff, W2R + wdf, b2 + vd, x, tmp,
                                           MROWS, DMODEL, DFF, 0, 0);
        ln_kernel<<<MROWS, 128>>>(tmp, g2 + vd, be2 + vd,
                                  (L == NLAYERS - 1) ? outp : x,
                                  (L == NLAYERS - 1) ? 0 : 1);
    }
}